// round 3
// baseline (speedup 1.0000x reference)
#include <cuda_runtime.h>
#include <math.h>

#define NMAX 100000

// ---------------- scratch (static __device__, per harness rules) -------------
__device__ float g_h1[NMAX * 64];
__device__ float g_asrc1[NMAX * 8];
__device__ float g_adst1[NMAX * 8];
__device__ float g_s1[NMAX * 8];
__device__ float g_out1[NMAX * 64];   // layer-1 aggregate; becomes hfeat in-place
__device__ float g_h2[NMAX * 40];
__device__ float g_asrc2[NMAX];
__device__ float g_adst2[NMAX];
__device__ float g_s2[NMAX];
__device__ float g_out2[NMAX * 40];

__device__ __forceinline__ void red_add_v4(float* addr, float a, float b, float c, float d) {
    asm volatile("red.global.add.v4.f32 [%0], {%1, %2, %3, %4};"
                 :: "l"(addr), "f"(a), "f"(b), "f"(c), "f"(d) : "memory");
}

// ---------------- tiled fp32 GEMM: C[M,BCOLS] = A[M,K] @ W[K,BCOLS] ---------
// 256-row blocks, microtile TM=8 x TN, A-fragment stored K-major in smem so
// both fragments load via LDS.128 (TN=8 case).
template <int BCOLS, int TN, int KTILE>
__global__ void gemm_kernel(const float* __restrict__ A, int M, int K,
                            const float* __restrict__ W, float* __restrict__ C) {
    constexpr int BROWS = 256;
    constexpr int TM = 8;
    constexpr int TX = BCOLS / TN;                    // 8
    constexpr int NT = TX * (BROWS / TM);             // 256
    constexpr int PAD = 4;

    __shared__ float xT[KTILE][BROWS + PAD];
    __shared__ float wS[KTILE][BCOLS];

    const int tid = threadIdx.x;
    const int tx = tid % TX;
    const int ty = tid / TX;
    const int row0 = blockIdx.x * BROWS;

    float acc[TM][TN];
#pragma unroll
    for (int i = 0; i < TM; i++)
#pragma unroll
        for (int j = 0; j < TN; j++) acc[i][j] = 0.0f;

    for (int kt = 0; kt < K; kt += KTILE) {
        // stage A tile (transposed into smem)
        constexpr int KV = KTILE / 4;
        constexpr int XV = BROWS * KV;
#pragma unroll
        for (int v = tid; v < XV; v += NT) {
            int r  = v / KV;
            int kv = v % KV;
            int grow = row0 + r;
            float4 f = make_float4(0.f, 0.f, 0.f, 0.f);
            if (grow < M)
                f = *reinterpret_cast<const float4*>(&A[(size_t)grow * K + kt + kv * 4]);
            xT[kv * 4 + 0][r] = f.x;
            xT[kv * 4 + 1][r] = f.y;
            xT[kv * 4 + 2][r] = f.z;
            xT[kv * 4 + 3][r] = f.w;
        }
        // stage W tile
        constexpr int WV = KTILE * BCOLS / 4;
#pragma unroll
        for (int v = tid; v < WV; v += NT) {
            int k = v / (BCOLS / 4);
            int c = v % (BCOLS / 4);
            *reinterpret_cast<float4*>(&wS[k][c * 4]) =
                *reinterpret_cast<const float4*>(&W[(size_t)(kt + k) * BCOLS + c * 4]);
        }
        __syncthreads();

#pragma unroll
        for (int k = 0; k < KTILE; k++) {
            float a[TM];
            *reinterpret_cast<float4*>(&a[0]) = *reinterpret_cast<float4*>(&xT[k][ty * TM]);
            *reinterpret_cast<float4*>(&a[4]) = *reinterpret_cast<float4*>(&xT[k][ty * TM + 4]);
            float b[TN];
            if constexpr (TN == 8) {
                *reinterpret_cast<float4*>(&b[0]) = *reinterpret_cast<float4*>(&wS[k][tx * 8]);
                *reinterpret_cast<float4*>(&b[4]) = *reinterpret_cast<float4*>(&wS[k][tx * 8 + 4]);
            } else {
#pragma unroll
                for (int j = 0; j < TN; j++) b[j] = wS[k][tx * TN + j];
            }
#pragma unroll
            for (int i = 0; i < TM; i++)
#pragma unroll
                for (int j = 0; j < TN; j++) acc[i][j] = fmaf(a[i], b[j], acc[i][j]);
        }
        __syncthreads();
    }

#pragma unroll
    for (int i = 0; i < TM; i++) {
        int grow = row0 + ty * TM + i;
        if (grow < M) {
            if constexpr (TN == 8) {
                *reinterpret_cast<float4*>(&C[(size_t)grow * BCOLS + tx * 8]) =
                    make_float4(acc[i][0], acc[i][1], acc[i][2], acc[i][3]);
                *reinterpret_cast<float4*>(&C[(size_t)grow * BCOLS + tx * 8 + 4]) =
                    make_float4(acc[i][4], acc[i][5], acc[i][6], acc[i][7]);
            } else {
#pragma unroll
                for (int j = 0; j < TN; j++) C[(size_t)grow * BCOLS + tx * TN + j] = acc[i][j];
            }
        }
    }
}

// ---------------- layer 1: per-node logits + zero accumulators --------------
__global__ void node_logits1(const float* __restrict__ att_src,
                             const float* __restrict__ att_dst, int n_nodes) {
    __shared__ float sa[64], sd[64];
    int tid = threadIdx.x;
    if (tid < 64) { sa[tid] = att_src[tid]; sd[tid] = att_dst[tid]; }
    __syncthreads();
    int n = blockIdx.x * blockDim.x + tid;
    if (n >= n_nodes) return;

    float row[64];
    const float4* hp = reinterpret_cast<const float4*>(&g_h1[(size_t)n * 64]);
#pragma unroll
    for (int i = 0; i < 16; i++) {
        float4 f = hp[i];
        row[i * 4 + 0] = f.x; row[i * 4 + 1] = f.y;
        row[i * 4 + 2] = f.z; row[i * 4 + 3] = f.w;
    }
#pragma unroll
    for (int h = 0; h < 8; h++) {
        float as = 0.f, ad = 0.f;
#pragma unroll
        for (int d = 0; d < 8; d++) {
            as = fmaf(row[h * 8 + d], sa[h * 8 + d], as);
            ad = fmaf(row[h * 8 + d], sd[h * 8 + d], ad);
        }
        g_asrc1[n * 8 + h] = as;
        g_adst1[n * 8 + h] = ad;
    }
    float4 z = make_float4(0.f, 0.f, 0.f, 0.f);
    float4* sp = reinterpret_cast<float4*>(&g_s1[n * 8]);
    sp[0] = z; sp[1] = z;
    float4* op = reinterpret_cast<float4*>(&g_out1[(size_t)n * 64]);
#pragma unroll
    for (int i = 0; i < 16; i++) op[i] = z;
}

// ---------------- layer 1: fused edge pass (exp-weighted scatter) -----------
// out[dst] += exp(lrelu(asrc[src]+adst[dst])) * h1[src];  s[dst] += w
// One thread per (edge, head). Self-loops are virtual edges e >= E.
__global__ void edge1_kernel(const int* __restrict__ ei, int E, int n_nodes) {
    int idx = blockIdx.x * blockDim.x + threadIdx.x;
    int total = (E + n_nodes) * 8;
    if (idx >= total) return;
    int e = idx >> 3;
    int hh = idx & 7;
    int src, dst;
    if (e < E) {
        src = ei[e];
        dst = ei[E + e];
    } else {
        src = dst = e - E;
    }
    float a = g_asrc1[src * 8 + hh] + g_adst1[dst * 8 + hh];
    a = a > 0.f ? a : 0.2f * a;
    float w = __expf(a);
    atomicAdd(&g_s1[dst * 8 + hh], w);
    const float4* hp = reinterpret_cast<const float4*>(&g_h1[(size_t)src * 64 + hh * 8]);
    float4 m0 = hp[0];
    float4 m1 = hp[1];
    red_add_v4(&g_out1[(size_t)dst * 64 + hh * 8],     w * m0.x, w * m0.y, w * m0.z, w * m0.w);
    red_add_v4(&g_out1[(size_t)dst * 64 + hh * 8 + 4], w * m1.x, w * m1.y, w * m1.z, w * m1.w);
}

// ---------------- layer 1: normalize + bias + ELU (in place) ----------------
__global__ void final1_kernel(const float* __restrict__ b1, int n_nodes) {
    __shared__ float sb[64];
    if (threadIdx.x < 64) sb[threadIdx.x] = b1[threadIdx.x];
    __syncthreads();
    int n = blockIdx.x * blockDim.x + threadIdx.x;
    if (n >= n_nodes) return;
    float inv[8];
    const float4* sp = reinterpret_cast<const float4*>(&g_s1[n * 8]);
    float4 s0 = sp[0], s1 = sp[1];
    inv[0] = 1.f / (s0.x + 1e-16f); inv[1] = 1.f / (s0.y + 1e-16f);
    inv[2] = 1.f / (s0.z + 1e-16f); inv[3] = 1.f / (s0.w + 1e-16f);
    inv[4] = 1.f / (s1.x + 1e-16f); inv[5] = 1.f / (s1.y + 1e-16f);
    inv[6] = 1.f / (s1.z + 1e-16f); inv[7] = 1.f / (s1.w + 1e-16f);
    float4* op = reinterpret_cast<float4*>(&g_out1[(size_t)n * 64]);
#pragma unroll
    for (int i = 0; i < 16; i++) {
        float4 f = op[i];
        float v[4] = {f.x, f.y, f.z, f.w};
#pragma unroll
        for (int j = 0; j < 4; j++) {
            int c = i * 4 + j;
            float t = v[j] * inv[c >> 3] + sb[c];
            v[j] = t > 0.f ? t : expm1f(t);     // ELU (alpha=1)
        }
        op[i] = make_float4(v[0], v[1], v[2], v[3]);
    }
}

// ---------------- layer 2: per-node logits + zero accumulators --------------
__global__ void node_logits2(const float* __restrict__ att_src,
                             const float* __restrict__ att_dst, int n_nodes) {
    __shared__ float sa[40], sd[40];
    int tid = threadIdx.x;
    if (tid < 40) { sa[tid] = att_src[tid]; sd[tid] = att_dst[tid]; }
    __syncthreads();
    int n = blockIdx.x * blockDim.x + tid;
    if (n >= n_nodes) return;
    const float4* hp = reinterpret_cast<const float4*>(&g_h2[(size_t)n * 40]);
    float as = 0.f, ad = 0.f;
#pragma unroll
    for (int i = 0; i < 10; i++) {
        float4 f = hp[i];
        as = fmaf(f.x, sa[i * 4 + 0], as); ad = fmaf(f.x, sd[i * 4 + 0], ad);
        as = fmaf(f.y, sa[i * 4 + 1], as); ad = fmaf(f.y, sd[i * 4 + 1], ad);
        as = fmaf(f.z, sa[i * 4 + 2], as); ad = fmaf(f.z, sd[i * 4 + 2], ad);
        as = fmaf(f.w, sa[i * 4 + 3], as); ad = fmaf(f.w, sd[i * 4 + 3], ad);
    }
    g_asrc2[n] = as;
    g_adst2[n] = ad;
    g_s2[n] = 0.f;
    float4 z = make_float4(0.f, 0.f, 0.f, 0.f);
    float4* op = reinterpret_cast<float4*>(&g_out2[(size_t)n * 40]);
#pragma unroll
    for (int i = 0; i < 10; i++) op[i] = z;
}

// ---------------- layer 2: fused edge pass ----------------------------------
// 8 threads per edge; slots 0..7 cover float4 chunks 0..7, slots 0..1 also
// cover chunks 8..9 (40 floats = 10 float4).
__global__ void edge2_kernel(const int* __restrict__ ei, int E, int n_nodes) {
    int idx = blockIdx.x * blockDim.x + threadIdx.x;
    int total = (E + n_nodes) * 8;
    if (idx >= total) return;
    int e = idx >> 3;
    int s = idx & 7;
    int src, dst;
    if (e < E) {
        src = ei[e];
        dst = ei[E + e];
    } else {
        src = dst = e - E;
    }
    float a = g_asrc2[src] + g_adst2[dst];
    a = a > 0.f ? a : 0.2f * a;
    float w = __expf(a);
    if (s == 0) atomicAdd(&g_s2[dst], w);
    const float4* hp = reinterpret_cast<const float4*>(&g_h2[(size_t)src * 40]);
    float4 v = hp[s];
    red_add_v4(&g_out2[(size_t)dst * 40 + s * 4], w * v.x, w * v.y, w * v.z, w * v.w);
    if (s < 2) {
        float4 v2 = hp[8 + s];
        red_add_v4(&g_out2[(size_t)dst * 40 + 32 + s * 4], w * v2.x, w * v2.y, w * v2.z, w * v2.w);
    }
}

// ---------------- layer 2: normalize + bias + log_softmax -> d_out ----------
// one warp per node (40 values: lanes 0..31 hold v0, lanes 0..7 also v1)
__global__ void final2_kernel(const float* __restrict__ b2, float* __restrict__ out,
                              int n_nodes) {
    int gt = blockIdx.x * blockDim.x + threadIdx.x;
    int node = gt >> 5;
    int lane = gt & 31;
    if (node >= n_nodes) return;
    float inv = 1.f / (g_s2[node] + 1e-16f);
    const float* orow = &g_out2[(size_t)node * 40];
    float v0 = orow[lane] * inv + b2[lane];
    float v1 = -3.4e38f;
    if (lane < 8) v1 = orow[32 + lane] * inv + b2[32 + lane];
    float m = fmaxf(v0, v1);
#pragma unroll
    for (int o = 16; o; o >>= 1) m = fmaxf(m, __shfl_xor_sync(0xffffffffu, m, o));
    float ssum = expf(v0 - m) + (lane < 8 ? expf(v1 - m) : 0.f);
#pragma unroll
    for (int o = 16; o; o >>= 1) ssum += __shfl_xor_sync(0xffffffffu, ssum, o);
    float lse = m + logf(ssum);
    float* dr = &out[(size_t)node * 40];
    dr[lane] = v0 - lse;
    if (lane < 8) dr[32 + lane] = v1 - lse;
}

// ---------------- launch -----------------------------------------------------
static inline int cdiv(int a, int b) { return (a + b - 1) / b; }

extern "C" void kernel_launch(void* const* d_in, const int* in_sizes, int n_in,
                              void* d_out, int out_size) {
    const float* x   = (const float*)d_in[0];
    const int*   ei  = (const int*)d_in[1];      // jax default: int64 downcast to int32
    const float* W1  = (const float*)d_in[2];
    const float* as1 = (const float*)d_in[3];
    const float* ad1 = (const float*)d_in[4];
    const float* b1  = (const float*)d_in[5];
    const float* W2  = (const float*)d_in[6];
    const float* as2 = (const float*)d_in[7];
    const float* ad2 = (const float*)d_in[8];
    const float* b2  = (const float*)d_in[9];
    float*       out = (float*)d_out;

    const int n = in_sizes[0] / 512;      // 100000
    const int E = in_sizes[1] / 2;        // 1600000

    float *p_h1, *p_out1, *p_h2;
    cudaGetSymbolAddress((void**)&p_h1,   g_h1);
    cudaGetSymbolAddress((void**)&p_out1, g_out1);
    cudaGetSymbolAddress((void**)&p_h2,   g_h2);

    const int nb_nodes = cdiv(n, 256);
    const int edge_threads = (E + n) * 8;
    const int nb_edges = cdiv(edge_threads, 256);

    // ---- layer 1 ----
    gemm_kernel<64, 8, 32><<<cdiv(n, 256), 256>>>(x, n, 512, W1, p_h1);
    node_logits1<<<nb_nodes, 256>>>(as1, ad1, n);
    edge1_kernel<<<nb_edges, 256>>>(ei, E, n);
    final1_kernel<<<nb_nodes, 256>>>(b1, n);          // g_out1 now = ELU(hfeat)

    // ---- layer 2 ----
    gemm_kernel<40, 5, 32><<<cdiv(n, 256), 256>>>(p_out1, n, 64, W2, p_h2);
    node_logits2<<<nb_nodes, 256>>>(as2, ad2, n);
    edge2_kernel<<<nb_edges, 256>>>(ei, E, n);
    final2_kernel<<<cdiv(n * 32, 256), 256>>>(b2, out, n);
}

// round 4
// speedup vs baseline: 1.2480x; 1.2480x over previous
#include <cuda_runtime.h>
#include <math.h>

#define NMAX 100000
#define EMAX 1600000

// ---------------- scratch (static __device__, per harness rules) -------------
__device__ float g_h1[NMAX * 64];       // layer-1 features (pre-aggregation)
__device__ float g_asrc1[NMAX * 8];
__device__ float g_adst1[NMAX * 8];
__device__ float g_hf1[NMAX * 64];      // layer-1 output after agg+bias+ELU
__device__ float g_h2[NMAX * 40];       // layer-2 features (pre-aggregation)
__device__ float g_asrc2[NMAX];
__device__ float g_adst2[NMAX];

__device__ int g_counts[NMAX];          // in-degree histogram (memset to 0 each call)
__device__ int g_cursor[NMAX];          // scatter cursors
__device__ int g_bsum[256];             // per-block partial sums for scan
__device__ int g_rowstart[NMAX + 1];    // CSR row offsets (by dst)
__device__ int g_srcs[EMAX];            // src node id, sorted by dst

// =======================  CSR build  ========================================

__global__ void hist_kernel(const int* __restrict__ ei, int E) {
    int e = blockIdx.x * blockDim.x + threadIdx.x;
    if (e >= E) return;
    atomicAdd(&g_counts[ei[E + e]], 1);
}

__global__ void scan_part1(int n) {               // block sums (1024 elems/block)
    __shared__ int sh[1024];
    int i = blockIdx.x * 1024 + threadIdx.x;
    sh[threadIdx.x] = (i < n) ? g_counts[i] : 0;
    __syncthreads();
#pragma unroll
    for (int off = 512; off; off >>= 1) {
        if (threadIdx.x < off) sh[threadIdx.x] += sh[threadIdx.x + off];
        __syncthreads();
    }
    if (threadIdx.x == 0) g_bsum[blockIdx.x] = sh[0];
}

__global__ void scan_part2(int nb, int n, int E) { // serial scan of block sums
    if (threadIdx.x == 0) {
        int run = 0;
        for (int b = 0; b < nb; b++) { int v = g_bsum[b]; g_bsum[b] = run; run += v; }
        g_rowstart[n] = E;
    }
}

__global__ void scan_part3(int n) {                // intra-block exclusive scan
    __shared__ int sh[1024];
    int t = threadIdx.x;
    int i = blockIdx.x * 1024 + t;
    int v = (i < n) ? g_counts[i] : 0;
    sh[t] = v;
    __syncthreads();
#pragma unroll
    for (int off = 1; off < 1024; off <<= 1) {
        int add = (t >= off) ? sh[t - off] : 0;
        __syncthreads();
        sh[t] += add;
        __syncthreads();
    }
    if (i < n) {
        int ex = sh[t] - v + g_bsum[blockIdx.x];
        g_rowstart[i] = ex;
        g_cursor[i]   = ex;
    }
}

__global__ void scatter_kernel(const int* __restrict__ ei, int E) {
    int e = blockIdx.x * blockDim.x + threadIdx.x;
    if (e >= E) return;
    int src = ei[e];
    int dst = ei[E + e];
    int pos = atomicAdd(&g_cursor[dst], 1);
    g_srcs[pos] = src;
}

// =======================  GEMM with fused attention logits  =================
// C[M,BCOLS] = A[M,K] @ W[K,BCOLS]; 256-row blocks, 8xTN microtile.
// HEADS==8: each thread's 8 cols = one head -> logits in registers.
// HEADS==1: 8-lane shfl_xor reduce across tx.
template <int BCOLS, int TN, int KTILE, int HEADS>
__global__ void gemm_kernel(const float* __restrict__ A, int M, int K,
                            const float* __restrict__ W, float* __restrict__ C,
                            const float* __restrict__ att_s, const float* __restrict__ att_d,
                            float* __restrict__ asrc, float* __restrict__ adst) {
    constexpr int BROWS = 256;
    constexpr int TM = 8;
    constexpr int TX = BCOLS / TN;                    // 8
    constexpr int NT = TX * (BROWS / TM);             // 256
    constexpr int PAD = 4;

    __shared__ float xT[KTILE][BROWS + PAD];
    __shared__ float wS[KTILE][BCOLS];
    __shared__ float sAs[BCOLS], sAd[BCOLS];

    const int tid = threadIdx.x;
    const int tx = tid % TX;
    const int ty = tid / TX;
    const int row0 = blockIdx.x * BROWS;

    if (tid < BCOLS) { sAs[tid] = att_s[tid]; sAd[tid] = att_d[tid]; }

    float acc[TM][TN];
#pragma unroll
    for (int i = 0; i < TM; i++)
#pragma unroll
        for (int j = 0; j < TN; j++) acc[i][j] = 0.0f;

    for (int kt = 0; kt < K; kt += KTILE) {
        constexpr int KV = KTILE / 4;
        constexpr int XV = BROWS * KV;
#pragma unroll
        for (int v = tid; v < XV; v += NT) {
            int r  = v / KV;
            int kv = v % KV;
            int grow = row0 + r;
            float4 f = make_float4(0.f, 0.f, 0.f, 0.f);
            if (grow < M)
                f = *reinterpret_cast<const float4*>(&A[(size_t)grow * K + kt + kv * 4]);
            xT[kv * 4 + 0][r] = f.x;
            xT[kv * 4 + 1][r] = f.y;
            xT[kv * 4 + 2][r] = f.z;
            xT[kv * 4 + 3][r] = f.w;
        }
        constexpr int WV = KTILE * BCOLS / 4;
#pragma unroll
        for (int v = tid; v < WV; v += NT) {
            int k = v / (BCOLS / 4);
            int c = v % (BCOLS / 4);
            *reinterpret_cast<float4*>(&wS[k][c * 4]) =
                *reinterpret_cast<const float4*>(&W[(size_t)(kt + k) * BCOLS + c * 4]);
        }
        __syncthreads();

#pragma unroll
        for (int k = 0; k < KTILE; k++) {
            float a[TM];
            *reinterpret_cast<float4*>(&a[0]) = *reinterpret_cast<float4*>(&xT[k][ty * TM]);
            *reinterpret_cast<float4*>(&a[4]) = *reinterpret_cast<float4*>(&xT[k][ty * TM + 4]);
            float b[TN];
            if constexpr (TN == 8) {
                *reinterpret_cast<float4*>(&b[0]) = *reinterpret_cast<float4*>(&wS[k][tx * 8]);
                *reinterpret_cast<float4*>(&b[4]) = *reinterpret_cast<float4*>(&wS[k][tx * 8 + 4]);
            } else {
#pragma unroll
                for (int j = 0; j < TN; j++) b[j] = wS[k][tx * TN + j];
            }
#pragma unroll
            for (int i = 0; i < TM; i++)
#pragma unroll
                for (int j = 0; j < TN; j++) acc[i][j] = fmaf(a[i], b[j], acc[i][j]);
        }
        __syncthreads();
    }

#pragma unroll
    for (int i = 0; i < TM; i++) {
        int grow = row0 + ty * TM + i;
        if (grow < M) {
            if constexpr (TN == 8) {
                *reinterpret_cast<float4*>(&C[(size_t)grow * BCOLS + tx * 8]) =
                    make_float4(acc[i][0], acc[i][1], acc[i][2], acc[i][3]);
                *reinterpret_cast<float4*>(&C[(size_t)grow * BCOLS + tx * 8 + 4]) =
                    make_float4(acc[i][4], acc[i][5], acc[i][6], acc[i][7]);
            } else {
#pragma unroll
                for (int j = 0; j < TN; j++) C[(size_t)grow * BCOLS + tx * TN + j] = acc[i][j];
            }
        }
        // fused attention logits
        if constexpr (HEADS == 8) {
            if (grow < M) {
                float as = 0.f, ad = 0.f;
#pragma unroll
                for (int j = 0; j < 8; j++) {
                    as = fmaf(acc[i][j], sAs[tx * 8 + j], as);
                    ad = fmaf(acc[i][j], sAd[tx * 8 + j], ad);
                }
                asrc[grow * 8 + tx] = as;
                adst[grow * 8 + tx] = ad;
            }
        } else {
            float as = 0.f, ad = 0.f;
#pragma unroll
            for (int j = 0; j < TN; j++) {
                as = fmaf(acc[i][j], sAs[tx * TN + j], as);
                ad = fmaf(acc[i][j], sAd[tx * TN + j], ad);
            }
#pragma unroll
            for (int off = 4; off; off >>= 1) {
                as += __shfl_xor_sync(0xffffffffu, as, off);
                ad += __shfl_xor_sync(0xffffffffu, ad, off);
            }
            if (tx == 0 && grow < M) { asrc[grow] = as; adst[grow] = ad; }
        }
    }
}

// =======================  layer-1 aggregation (warp per dst)  ===============
// out[dst] = ELU( (sum_e w_e * h1[src_e]) / (sum_e w_e) + b1 ),  w = exp(lrelu(.))
__global__ void agg1_kernel(const float* __restrict__ b1, int n) {
    int node = (blockIdx.x * blockDim.x + threadIdx.x) >> 5;
    int lane = threadIdx.x & 31;
    if (node >= n) return;

    float adst = (lane < 8) ? g_adst1[node * 8 + lane] : 0.f;
    float acc0 = 0.f, acc1 = 0.f, ssum = 0.f;
    const int h0 = lane >> 3;          // head for feature 'lane'      (0..3)
    const int h1 = 4 + (lane >> 3);    // head for feature 'lane+32'   (4..7)

    int beg = g_rowstart[node], end = g_rowstart[node + 1];
    for (int base = beg; base < end; base += 32) {
        int cnt = min(32, end - base);
        int sl = (base + lane < end) ? g_srcs[base + lane] : 0;
        for (int d = 0; d < cnt; d++) {
            int src = __shfl_sync(0xffffffffu, sl, d);
            float w8 = 0.f;
            if (lane < 8) {
                float a = g_asrc1[src * 8 + lane] + adst;
                a = a > 0.f ? a : 0.2f * a;
                w8 = __expf(a);
                ssum += w8;
            }
            float w0 = __shfl_sync(0xffffffffu, w8, h0);
            float w1 = __shfl_sync(0xffffffffu, w8, h1);
            acc0 = fmaf(w0, g_h1[(size_t)src * 64 + lane],      acc0);
            acc1 = fmaf(w1, g_h1[(size_t)src * 64 + 32 + lane], acc1);
        }
    }
    // self loop
    {
        float w8 = 0.f;
        if (lane < 8) {
            float a = g_asrc1[node * 8 + lane] + adst;
            a = a > 0.f ? a : 0.2f * a;
            w8 = __expf(a);
            ssum += w8;
        }
        float w0 = __shfl_sync(0xffffffffu, w8, h0);
        float w1 = __shfl_sync(0xffffffffu, w8, h1);
        acc0 = fmaf(w0, g_h1[(size_t)node * 64 + lane],      acc0);
        acc1 = fmaf(w1, g_h1[(size_t)node * 64 + 32 + lane], acc1);
    }
    float s0 = __shfl_sync(0xffffffffu, ssum, h0);
    float s1 = __shfl_sync(0xffffffffu, ssum, h1);
    float t0 = acc0 / (s0 + 1e-16f) + b1[lane];
    float t1 = acc1 / (s1 + 1e-16f) + b1[32 + lane];
    t0 = t0 > 0.f ? t0 : expm1f(t0);
    t1 = t1 > 0.f ? t1 : expm1f(t1);
    g_hf1[(size_t)node * 64 + lane]      = t0;
    g_hf1[(size_t)node * 64 + 32 + lane] = t1;
}

// =======================  layer-2 aggregation + log_softmax  ================
__global__ void agg2_kernel(const float* __restrict__ b2, float* __restrict__ out, int n) {
    int node = (blockIdx.x * blockDim.x + threadIdx.x) >> 5;
    int lane = threadIdx.x & 31;
    if (node >= n) return;

    float adst = g_adst2[node];
    float acc0 = 0.f, acc1 = 0.f, ssum = 0.f;

    int beg = g_rowstart[node], end = g_rowstart[node + 1];
    for (int base = beg; base < end; base += 32) {
        int cnt = min(32, end - base);
        int sl = 0;
        float wl = 0.f;
        if (base + lane < end) {
            sl = g_srcs[base + lane];
            float a = g_asrc2[sl] + adst;
            a = a > 0.f ? a : 0.2f * a;
            wl = __expf(a);
            ssum += wl;
        }
        for (int d = 0; d < cnt; d++) {
            int src = __shfl_sync(0xffffffffu, sl, d);
            float w  = __shfl_sync(0xffffffffu, wl, d);
            acc0 = fmaf(w, g_h2[(size_t)src * 40 + lane], acc0);
            if (lane < 8)
                acc1 = fmaf(w, g_h2[(size_t)src * 40 + 32 + lane], acc1);
        }
    }
    // warp-reduce ssum
#pragma unroll
    for (int o = 16; o; o >>= 1) ssum += __shfl_xor_sync(0xffffffffu, ssum, o);
    // self loop (scalar, all lanes)
    {
        float a = g_asrc2[node] + adst;
        a = a > 0.f ? a : 0.2f * a;
        float w = __expf(a);
        ssum += w;
        acc0 = fmaf(w, g_h2[(size_t)node * 40 + lane], acc0);
        if (lane < 8)
            acc1 = fmaf(w, g_h2[(size_t)node * 40 + 32 + lane], acc1);
    }
    float inv = 1.f / (ssum + 1e-16f);
    float v0 = acc0 * inv + b2[lane];
    float v1 = (lane < 8) ? acc1 * inv + b2[32 + lane] : -3.4e38f;

    float m = fmaxf(v0, v1);
#pragma unroll
    for (int o = 16; o; o >>= 1) m = fmaxf(m, __shfl_xor_sync(0xffffffffu, m, o));
    float es = expf(v0 - m) + (lane < 8 ? expf(v1 - m) : 0.f);
#pragma unroll
    for (int o = 16; o; o >>= 1) es += __shfl_xor_sync(0xffffffffu, es, o);
    float lse = m + logf(es);

    float* dr = &out[(size_t)node * 40];
    dr[lane] = v0 - lse;
    if (lane < 8) dr[32 + lane] = v1 - lse;
}

// ---------------- launch -----------------------------------------------------
static inline int cdiv(int a, int b) { return (a + b - 1) / b; }

extern "C" void kernel_launch(void* const* d_in, const int* in_sizes, int n_in,
                              void* d_out, int out_size) {
    const float* x   = (const float*)d_in[0];
    const int*   ei  = (const int*)d_in[1];      // int32 on device
    const float* W1  = (const float*)d_in[2];
    const float* as1 = (const float*)d_in[3];
    const float* ad1 = (const float*)d_in[4];
    const float* b1  = (const float*)d_in[5];
    const float* W2  = (const float*)d_in[6];
    const float* as2 = (const float*)d_in[7];
    const float* ad2 = (const float*)d_in[8];
    const float* b2  = (const float*)d_in[9];
    float*       out = (float*)d_out;

    const int n = in_sizes[0] / 512;      // 100000
    const int E = in_sizes[1] / 2;        // 1600000

    float *p_h1, *p_hf1, *p_h2, *p_as1, *p_ad1, *p_as2, *p_ad2;
    void* p_counts;
    cudaGetSymbolAddress((void**)&p_h1,  g_h1);
    cudaGetSymbolAddress((void**)&p_hf1, g_hf1);
    cudaGetSymbolAddress((void**)&p_h2,  g_h2);
    cudaGetSymbolAddress((void**)&p_as1, g_asrc1);
    cudaGetSymbolAddress((void**)&p_ad1, g_adst1);
    cudaGetSymbolAddress((void**)&p_as2, g_asrc2);
    cudaGetSymbolAddress((void**)&p_ad2, g_adst2);
    cudaGetSymbolAddress(&p_counts, g_counts);

    const int nb_scan = cdiv(n, 1024);

    // ---- CSR build (sort edges by dst) ----
    cudaMemsetAsync(p_counts, 0, n * sizeof(int));
    hist_kernel<<<cdiv(E, 256), 256>>>(ei, E);
    scan_part1<<<nb_scan, 1024>>>(n);
    scan_part2<<<1, 32>>>(nb_scan, n, E);
    scan_part3<<<nb_scan, 1024>>>(n);
    scatter_kernel<<<cdiv(E, 256), 256>>>(ei, E);

    // ---- layer 1 ----
    gemm_kernel<64, 8, 32, 8><<<cdiv(n, 256), 256>>>(x, n, 512, W1, p_h1,
                                                     as1, ad1, p_as1, p_ad1);
    agg1_kernel<<<cdiv(n * 32, 256), 256>>>(b1, n);

    // ---- layer 2 ----
    gemm_kernel<40, 5, 32, 1><<<cdiv(n, 256), 256>>>(p_hf1, n, 64, W2, p_h2,
                                                     as2, ad2, p_as2, p_ad2);
    agg2_kernel<<<cdiv(n * 32, 256), 256>>>(b2, out, n);
}

// round 5
// speedup vs baseline: 1.2773x; 1.0235x over previous
#include <cuda_runtime.h>
#include <math.h>

#define NMAX 100000
#define EMAX 1600000

// ---------------- scratch (static __device__, per harness rules) -------------
__device__ float g_h1[NMAX * 64];       // layer-1 features (pre-aggregation)
__device__ float g_asrc1[NMAX * 8];
__device__ float g_adst1[NMAX * 8];
__device__ float g_hf1[NMAX * 64];      // layer-1 output after agg+bias+ELU
__device__ float g_h2[NMAX * 40];       // layer-2 features (pre-aggregation)
__device__ float g_asrc2[NMAX];
__device__ float g_adst2[NMAX];

__device__ int g_counts[NMAX];          // in-degree histogram (memset to 0 each call)
__device__ int g_cursor[NMAX];          // scatter cursors
__device__ int g_bsum[256];             // per-block partial sums for scan
__device__ int g_rowstart[NMAX + 1];    // CSR row offsets (by dst)
__device__ int g_srcs[EMAX];            // src node id, sorted by dst

// =======================  CSR build  ========================================

__global__ void hist_kernel(const int* __restrict__ ei, int E) {
    int e = blockIdx.x * blockDim.x + threadIdx.x;
    if (e >= E) return;
    atomicAdd(&g_counts[ei[E + e]], 1);
}

__global__ void scan_part1(int n) {               // block sums (1024 elems/block)
    __shared__ int sh[1024];
    int i = blockIdx.x * 1024 + threadIdx.x;
    sh[threadIdx.x] = (i < n) ? g_counts[i] : 0;
    __syncthreads();
#pragma unroll
    for (int off = 512; off; off >>= 1) {
        if (threadIdx.x < off) sh[threadIdx.x] += sh[threadIdx.x + off];
        __syncthreads();
    }
    if (threadIdx.x == 0) g_bsum[blockIdx.x] = sh[0];
}

__global__ void scan_part2(int nb, int n, int E) { // serial scan of block sums
    if (threadIdx.x == 0) {
        int run = 0;
        for (int b = 0; b < nb; b++) { int v = g_bsum[b]; g_bsum[b] = run; run += v; }
        g_rowstart[n] = E;
    }
}

__global__ void scan_part3(int n) {                // intra-block exclusive scan
    __shared__ int sh[1024];
    int t = threadIdx.x;
    int i = blockIdx.x * 1024 + t;
    int v = (i < n) ? g_counts[i] : 0;
    sh[t] = v;
    __syncthreads();
#pragma unroll
    for (int off = 1; off < 1024; off <<= 1) {
        int add = (t >= off) ? sh[t - off] : 0;
        __syncthreads();
        sh[t] += add;
        __syncthreads();
    }
    if (i < n) {
        int ex = sh[t] - v + g_bsum[blockIdx.x];
        g_rowstart[i] = ex;
        g_cursor[i]   = ex;
    }
}

__global__ void scatter_kernel(const int* __restrict__ ei, int E) {
    int e = blockIdx.x * blockDim.x + threadIdx.x;
    if (e >= E) return;
    int src = ei[e];
    int dst = ei[E + e];
    int pos = atomicAdd(&g_cursor[dst], 1);
    g_srcs[pos] = src;
}

// =======================  GEMM with fused attention logits  =================
template <int BCOLS, int TN, int KTILE, int HEADS>
__global__ void gemm_kernel(const float* __restrict__ A, int M, int K,
                            const float* __restrict__ W, float* __restrict__ C,
                            const float* __restrict__ att_s, const float* __restrict__ att_d,
                            float* __restrict__ asrc, float* __restrict__ adst) {
    constexpr int BROWS = 256;
    constexpr int TM = 8;
    constexpr int TX = BCOLS / TN;                    // 8
    constexpr int NT = TX * (BROWS / TM);             // 256
    constexpr int PAD = 4;

    __shared__ float xT[KTILE][BROWS + PAD];
    __shared__ float wS[KTILE][BCOLS];
    __shared__ float sAs[BCOLS], sAd[BCOLS];

    const int tid = threadIdx.x;
    const int tx = tid % TX;
    const int ty = tid / TX;
    const int row0 = blockIdx.x * BROWS;

    if (tid < BCOLS) { sAs[tid] = att_s[tid]; sAd[tid] = att_d[tid]; }

    float acc[TM][TN];
#pragma unroll
    for (int i = 0; i < TM; i++)
#pragma unroll
        for (int j = 0; j < TN; j++) acc[i][j] = 0.0f;

    for (int kt = 0; kt < K; kt += KTILE) {
        constexpr int KV = KTILE / 4;
        constexpr int XV = BROWS * KV;
#pragma unroll
        for (int v = tid; v < XV; v += NT) {
            int r  = v / KV;
            int kv = v % KV;
            int grow = row0 + r;
            float4 f = make_float4(0.f, 0.f, 0.f, 0.f);
            if (grow < M)
                f = *reinterpret_cast<const float4*>(&A[(size_t)grow * K + kt + kv * 4]);
            xT[kv * 4 + 0][r] = f.x;
            xT[kv * 4 + 1][r] = f.y;
            xT[kv * 4 + 2][r] = f.z;
            xT[kv * 4 + 3][r] = f.w;
        }
        constexpr int WV = KTILE * BCOLS / 4;
#pragma unroll
        for (int v = tid; v < WV; v += NT) {
            int k = v / (BCOLS / 4);
            int c = v % (BCOLS / 4);
            *reinterpret_cast<float4*>(&wS[k][c * 4]) =
                *reinterpret_cast<const float4*>(&W[(size_t)(kt + k) * BCOLS + c * 4]);
        }
        __syncthreads();

#pragma unroll
        for (int k = 0; k < KTILE; k++) {
            float a[TM];
            *reinterpret_cast<float4*>(&a[0]) = *reinterpret_cast<float4*>(&xT[k][ty * TM]);
            *reinterpret_cast<float4*>(&a[4]) = *reinterpret_cast<float4*>(&xT[k][ty * TM + 4]);
            float b[TN];
            if constexpr (TN == 8) {
                *reinterpret_cast<float4*>(&b[0]) = *reinterpret_cast<float4*>(&wS[k][tx * 8]);
                *reinterpret_cast<float4*>(&b[4]) = *reinterpret_cast<float4*>(&wS[k][tx * 8 + 4]);
            } else {
#pragma unroll
                for (int j = 0; j < TN; j++) b[j] = wS[k][tx * TN + j];
            }
#pragma unroll
            for (int i = 0; i < TM; i++)
#pragma unroll
                for (int j = 0; j < TN; j++) acc[i][j] = fmaf(a[i], b[j], acc[i][j]);
        }
        __syncthreads();
    }

#pragma unroll
    for (int i = 0; i < TM; i++) {
        int grow = row0 + ty * TM + i;
        if (grow < M) {
            if constexpr (TN == 8) {
                *reinterpret_cast<float4*>(&C[(size_t)grow * BCOLS + tx * 8]) =
                    make_float4(acc[i][0], acc[i][1], acc[i][2], acc[i][3]);
                *reinterpret_cast<float4*>(&C[(size_t)grow * BCOLS + tx * 8 + 4]) =
                    make_float4(acc[i][4], acc[i][5], acc[i][6], acc[i][7]);
            } else {
#pragma unroll
                for (int j = 0; j < TN; j++) C[(size_t)grow * BCOLS + tx * TN + j] = acc[i][j];
            }
        }
        // fused attention logits
        if constexpr (HEADS == 8) {
            if (grow < M) {
                float as = 0.f, ad = 0.f;
#pragma unroll
                for (int j = 0; j < 8; j++) {
                    as = fmaf(acc[i][j], sAs[tx * 8 + j], as);
                    ad = fmaf(acc[i][j], sAd[tx * 8 + j], ad);
                }
                asrc[grow * 8 + tx] = as;
                adst[grow * 8 + tx] = ad;
            }
        } else {
            float as = 0.f, ad = 0.f;
#pragma unroll
            for (int j = 0; j < TN; j++) {
                as = fmaf(acc[i][j], sAs[tx * TN + j], as);
                ad = fmaf(acc[i][j], sAd[tx * TN + j], ad);
            }
#pragma unroll
            for (int off = 4; off; off >>= 1) {
                as += __shfl_xor_sync(0xffffffffu, as, off);
                ad += __shfl_xor_sync(0xffffffffu, ad, off);
            }
            if (tx == 0 && grow < M) { asrc[grow] = as; adst[grow] = ad; }
        }
    }
}

// =======================  layer-1 aggregation (warp per dst)  ===============
// Vectorized weights: all 32 lanes compute (4 edges x 8 heads) per step, so
// the accumulation sub-loop's shfls read ready registers (no LDG dependency).
__global__ void agg1_kernel(const float* __restrict__ b1, int n) {
    int node = (blockIdx.x * blockDim.x + threadIdx.x) >> 5;
    int lane = threadIdx.x & 31;
    if (node >= n) return;

    const int myh = lane & 7;           // head this lane computes weights for
    const int grp = lane >> 3;          // edge slot within 4-edge chunk
    const int h0 = lane >> 3;           // head of feature 'lane'      (0..3)
    const int h1f = 4 + (lane >> 3);    // head of feature 'lane+32'   (4..7)

    float adst_l = g_adst1[node * 8 + myh];
    float acc0 = 0.f, acc1 = 0.f, wsum = 0.f;

    int beg = g_rowstart[node], end = g_rowstart[node + 1];
    for (int base = beg; base < end; base += 32) {
        int cnt = min(32, end - base);
        int li = base + lane; if (li >= end) li = end - 1;
        int sl = g_srcs[li];
        int nch = (cnt + 3) >> 2;
        for (int c = 0; c < nch; c++) {
            int eslot = c * 4 + grp;
            int esrc = __shfl_sync(0xffffffffu, sl, eslot < cnt ? eslot : 0);
            float w = 0.f;
            if (eslot < cnt) {
                float a = g_asrc1[esrc * 8 + myh] + adst_l;
                a = a > 0.f ? a : 0.2f * a;
                w = __expf(a);
                wsum += w;
            }
            int dmax = min(4, cnt - c * 4);
#pragma unroll 4
            for (int dd = 0; dd < dmax; dd++) {
                int src = __shfl_sync(0xffffffffu, sl, c * 4 + dd);
                float w0 = __shfl_sync(0xffffffffu, w, dd * 8 + h0);
                float w1 = __shfl_sync(0xffffffffu, w, dd * 8 + h1f);
                const float* hp = &g_h1[(size_t)src * 64];
                acc0 = fmaf(w0, hp[lane],      acc0);
                acc1 = fmaf(w1, hp[32 + lane], acc1);
            }
        }
    }
    // reduce wsum over the 4 edge-slot replicas (lanes differing in bits 3,4)
    wsum += __shfl_xor_sync(0xffffffffu, wsum, 8);
    wsum += __shfl_xor_sync(0xffffffffu, wsum, 16);
    // self loop (every lane computes its head's weight; replicas consistent)
    {
        float a = g_asrc1[node * 8 + myh] + adst_l;
        a = a > 0.f ? a : 0.2f * a;
        float wself = __expf(a);
        wsum += wself;
        float w0 = __shfl_sync(0xffffffffu, wself, h0);
        float w1 = __shfl_sync(0xffffffffu, wself, h1f);
        const float* hp = &g_h1[(size_t)node * 64];
        acc0 = fmaf(w0, hp[lane],      acc0);
        acc1 = fmaf(w1, hp[32 + lane], acc1);
    }
    float s0 = __shfl_sync(0xffffffffu, wsum, h0);
    float s1 = __shfl_sync(0xffffffffu, wsum, h1f);
    float t0 = acc0 / (s0 + 1e-16f) + b1[lane];
    float t1 = acc1 / (s1 + 1e-16f) + b1[32 + lane];
    t0 = t0 > 0.f ? t0 : expm1f(t0);
    t1 = t1 > 0.f ? t1 : expm1f(t1);
    g_hf1[(size_t)node * 64 + lane]      = t0;
    g_hf1[(size_t)node * 64 + 32 + lane] = t1;
}

// =======================  layer-2 aggregation + log_softmax  ================
__global__ void agg2_kernel(const float* __restrict__ b2, float* __restrict__ out, int n) {
    int node = (blockIdx.x * blockDim.x + threadIdx.x) >> 5;
    int lane = threadIdx.x & 31;
    if (node >= n) return;

    float adst = g_adst2[node];
    float acc0 = 0.f, acc1 = 0.f, ssum = 0.f;

    int beg = g_rowstart[node], end = g_rowstart[node + 1];
    for (int base = beg; base < end; base += 32) {
        int cnt = min(32, end - base);
        int sl = 0;
        float wl = 0.f;
        if (base + lane < end) {
            sl = g_srcs[base + lane];
            float a = g_asrc2[sl] + adst;
            a = a > 0.f ? a : 0.2f * a;
            wl = __expf(a);
            ssum += wl;
        }
        for (int d = 0; d < cnt; d++) {
            int src = __shfl_sync(0xffffffffu, sl, d);
            float w  = __shfl_sync(0xffffffffu, wl, d);
            acc0 = fmaf(w, g_h2[(size_t)src * 40 + lane], acc0);
            if (lane < 8)
                acc1 = fmaf(w, g_h2[(size_t)src * 40 + 32 + lane], acc1);
        }
    }
#pragma unroll
    for (int o = 16; o; o >>= 1) ssum += __shfl_xor_sync(0xffffffffu, ssum, o);
    // self loop
    {
        float a = g_asrc2[node] + adst;
        a = a > 0.f ? a : 0.2f * a;
        float w = __expf(a);
        ssum += w;
        acc0 = fmaf(w, g_h2[(size_t)node * 40 + lane], acc0);
        if (lane < 8)
            acc1 = fmaf(w, g_h2[(size_t)node * 40 + 32 + lane], acc1);
    }
    float inv = 1.f / (ssum + 1e-16f);
    float v0 = acc0 * inv + b2[lane];
    float v1 = (lane < 8) ? acc1 * inv + b2[32 + lane] : -3.4e38f;

    float m = fmaxf(v0, v1);
#pragma unroll
    for (int o = 16; o; o >>= 1) m = fmaxf(m, __shfl_xor_sync(0xffffffffu, m, o));
    float es = expf(v0 - m) + (lane < 8 ? expf(v1 - m) : 0.f);
#pragma unroll
    for (int o = 16; o; o >>= 1) es += __shfl_xor_sync(0xffffffffu, es, o);
    float lse = m + logf(es);

    float* dr = &out[(size_t)node * 40];
    dr[lane] = v0 - lse;
    if (lane < 8) dr[32 + lane] = v1 - lse;
}

// ---------------- launch -----------------------------------------------------
static inline int cdiv(int a, int b) { return (a + b - 1) / b; }

extern "C" void kernel_launch(void* const* d_in, const int* in_sizes, int n_in,
                              void* d_out, int out_size) {
    const float* x   = (const float*)d_in[0];
    const int*   ei  = (const int*)d_in[1];      // int32 on device
    const float* W1  = (const float*)d_in[2];
    const float* as1 = (const float*)d_in[3];
    const float* ad1 = (const float*)d_in[4];
    const float* b1  = (const float*)d_in[5];
    const float* W2  = (const float*)d_in[6];
    const float* as2 = (const float*)d_in[7];
    const float* ad2 = (const float*)d_in[8];
    const float* b2  = (const float*)d_in[9];
    float*       out = (float*)d_out;

    const int n = in_sizes[0] / 512;      // 100000
    const int E = in_sizes[1] / 2;        // 1600000

    float *p_h1, *p_hf1, *p_h2, *p_as1, *p_ad1, *p_as2, *p_ad2;
    void* p_counts;
    cudaGetSymbolAddress((void**)&p_h1,  g_h1);
    cudaGetSymbolAddress((void**)&p_hf1, g_hf1);
    cudaGetSymbolAddress((void**)&p_h2,  g_h2);
    cudaGetSymbolAddress((void**)&p_as1, g_asrc1);
    cudaGetSymbolAddress((void**)&p_ad1, g_adst1);
    cudaGetSymbolAddress((void**)&p_as2, g_asrc2);
    cudaGetSymbolAddress((void**)&p_ad2, g_adst2);
    cudaGetSymbolAddress(&p_counts, g_counts);

    // side stream + fork/join events (created once, on the uncaptured
    // correctness call; reused deterministically every call)
    static cudaStream_t s1 = nullptr;
    static cudaEvent_t ev_fork = nullptr, ev_join = nullptr;
    if (s1 == nullptr) {
        cudaStreamCreateWithFlags(&s1, cudaStreamNonBlocking);
        cudaEventCreateWithFlags(&ev_fork, cudaEventDisableTiming);
        cudaEventCreateWithFlags(&ev_join, cudaEventDisableTiming);
    }

    const int nb_scan = cdiv(n, 1024);

    // ---- fork: CSR build on s1, concurrent with gemm1 on default stream ----
    cudaEventRecord(ev_fork, 0);
    cudaStreamWaitEvent(s1, ev_fork, 0);

    cudaMemsetAsync(p_counts, 0, n * sizeof(int), s1);
    hist_kernel<<<cdiv(E, 256), 256, 0, s1>>>(ei, E);
    scan_part1<<<nb_scan, 1024, 0, s1>>>(n);
    scan_part2<<<1, 32, 0, s1>>>(nb_scan, n, E);
    scan_part3<<<nb_scan, 1024, 0, s1>>>(n);
    scatter_kernel<<<cdiv(E, 256), 256, 0, s1>>>(ei, E);
    cudaEventRecord(ev_join, s1);

    // ---- layer-1 GEMM (default stream, overlaps CSR build) ----
    gemm_kernel<64, 8, 32, 8><<<cdiv(n, 256), 256>>>(x, n, 512, W1, p_h1,
                                                     as1, ad1, p_as1, p_ad1);

    // ---- join, then aggregation + layer 2 ----
    cudaStreamWaitEvent(0, ev_join, 0);
    agg1_kernel<<<cdiv(n * 32, 256), 256>>>(b1, n);
    gemm_kernel<40, 5, 32, 1><<<cdiv(n, 256), 256>>>(p_hf1, n, 64, W2, p_h2,
                                                     as2, ad2, p_as2, p_ad2);
    agg2_kernel<<<cdiv(n * 32, 256), 256>>>(b2, out, n);
}

// round 6
// speedup vs baseline: 1.7171x; 1.3443x over previous
#include <cuda_runtime.h>
#include <math.h>
#include <stdint.h>

#define NMAX 100000
#define EMAX 1600000

// ---------------- scratch (static __device__, per harness rules) -------------
__device__ float g_h1[NMAX * 64];       // layer-1 features (pre-aggregation)
__device__ float g_asrc1[NMAX * 8];
__device__ float g_adst1[NMAX * 8];
__device__ float g_hf1[NMAX * 64];      // layer-1 output after agg+bias+ELU
__device__ float g_h2[NMAX * 40];       // layer-2 features (pre-aggregation)
__device__ float g_asrc2[NMAX];
__device__ float g_adst2[NMAX];

__device__ int g_counts[NMAX];
__device__ int g_cursor[NMAX];
__device__ int g_bsum[256];
__device__ int g_rowstart[NMAX + 1];
__device__ int g_srcs[EMAX];

// =======================  CSR build  ========================================

__global__ void hist_kernel(const int* __restrict__ ei, int E) {
    int e = blockIdx.x * blockDim.x + threadIdx.x;
    if (e >= E) return;
    atomicAdd(&g_counts[ei[E + e]], 1);
}

__global__ void scan_part1(int n) {
    __shared__ int sh[1024];
    int i = blockIdx.x * 1024 + threadIdx.x;
    sh[threadIdx.x] = (i < n) ? g_counts[i] : 0;
    __syncthreads();
#pragma unroll
    for (int off = 512; off; off >>= 1) {
        if (threadIdx.x < off) sh[threadIdx.x] += sh[threadIdx.x + off];
        __syncthreads();
    }
    if (threadIdx.x == 0) g_bsum[blockIdx.x] = sh[0];
}

__global__ void scan_part2(int nb, int n, int E) {
    if (threadIdx.x == 0) {
        int run = 0;
        for (int b = 0; b < nb; b++) { int v = g_bsum[b]; g_bsum[b] = run; run += v; }
        g_rowstart[n] = E;
    }
}

__global__ void scan_part3(int n) {
    __shared__ int sh[1024];
    int t = threadIdx.x;
    int i = blockIdx.x * 1024 + t;
    int v = (i < n) ? g_counts[i] : 0;
    sh[t] = v;
    __syncthreads();
#pragma unroll
    for (int off = 1; off < 1024; off <<= 1) {
        int add = (t >= off) ? sh[t - off] : 0;
        __syncthreads();
        sh[t] += add;
        __syncthreads();
    }
    if (i < n) {
        int ex = sh[t] - v + g_bsum[blockIdx.x];
        g_rowstart[i] = ex;
        g_cursor[i]   = ex;
    }
}

__global__ void scatter_kernel(const int* __restrict__ ei, int E) {
    int e = blockIdx.x * blockDim.x + threadIdx.x;
    if (e >= E) return;
    int src = ei[e];
    int dst = ei[E + e];
    int pos = atomicAdd(&g_cursor[dst], 1);
    g_srcs[pos] = src;
}

// =======================  tf32 helpers  =====================================

__device__ __forceinline__ uint32_t f2tf32(float v) {
    uint32_t r;
    asm("cvt.rna.tf32.f32 %0, %1;" : "=r"(r) : "f"(v));
    return r;
}

__device__ __forceinline__ void mma_tf32(float& c0, float& c1, float& c2, float& c3,
                                         uint32_t a0, uint32_t a1, uint32_t a2, uint32_t a3,
                                         uint32_t b0, uint32_t b1) {
    asm volatile("mma.sync.aligned.m16n8k8.row.col.f32.tf32.tf32.f32 "
                 "{%0,%1,%2,%3}, {%4,%5,%6,%7}, {%8,%9}, {%0,%1,%2,%3};"
                 : "+f"(c0), "+f"(c1), "+f"(c2), "+f"(c3)
                 : "r"(a0), "r"(a1), "r"(a2), "r"(a3), "r"(b0), "r"(b1));
}

// =======================  layer-1 GEMM: tf32 3-pass MMA  ====================
// C[M,64] = A[M,512] @ W[512,64]  via (Ah+Al)(Wh+Wl) ~= AhWh + AlWh + AhWl.
// Block 128x64 tile, 256 threads = 8 warps (4x2), warp tile 32x32.
// Fused epilogue: per-row attention logits for 8 heads.
__global__ __launch_bounds__(256, 2)
void gemm1_tf32(const float* __restrict__ A, int M,
                const float* __restrict__ W, float* __restrict__ C,
                const float* __restrict__ att_s, const float* __restrict__ att_d,
                float* __restrict__ asrc, float* __restrict__ adst) {
    constexpr int BM = 128, BN = 64, BK = 16;
    constexpr int ASTR = BK + 4;   // 20: (20*r + k) % 32 all-distinct -> conflict-free
    constexpr int BSTR = BN + 8;   // 72: (8*k + c) % 32 all-distinct -> conflict-free

    __shared__ float Ah_s[BM * ASTR], Al_s[BM * ASTR];
    __shared__ float Wh_s[BK * BSTR], Wl_s[BK * BSTR];

    const int tid  = threadIdx.x;
    const int lane = tid & 31;
    const int warp = tid >> 5;
    const int wrow = warp >> 1;          // 0..3
    const int wcol = warp & 1;           // 0..1
    const int row0 = blockIdx.x * BM;
    const int qt   = lane & 3;           // thread column-quad within row group
    const int rg   = lane >> 2;          // row group 0..7

    float acc[2][4][4];
#pragma unroll
    for (int mt = 0; mt < 2; mt++)
#pragma unroll
        for (int nt = 0; nt < 4; nt++)
#pragma unroll
            for (int r = 0; r < 4; r++) acc[mt][nt][r] = 0.f;

    for (int kt = 0; kt < 512; kt += BK) {
        // ---- stage A (hi/lo), row-major [row][k], 2 float4 per thread ----
#pragma unroll
        for (int i = 0; i < 2; i++) {
            int idx = tid + i * 256;         // 0..511
            int row = idx >> 2;              // 0..127
            int kq  = idx & 3;               // float4 index within BK=16
            float4 f = make_float4(0.f, 0.f, 0.f, 0.f);
            int grow = row0 + row;
            if (grow < M)
                f = *reinterpret_cast<const float4*>(&A[(size_t)grow * 512 + kt + kq * 4]);
            float vv[4] = {f.x, f.y, f.z, f.w};
#pragma unroll
            for (int j = 0; j < 4; j++) {
                uint32_t hb = f2tf32(vv[j]);
                float lo = vv[j] - __uint_as_float(hb);
                Ah_s[row * ASTR + kq * 4 + j] = __uint_as_float(hb);
                Al_s[row * ASTR + kq * 4 + j] = __uint_as_float(f2tf32(lo));
            }
        }
        // ---- stage W (hi/lo), k-major [k][c], 1 float4 per thread ----
        {
            int k  = tid >> 4;               // 0..15
            int c4 = tid & 15;               // 0..15
            float4 f = *reinterpret_cast<const float4*>(&W[(size_t)(kt + k) * 64 + c4 * 4]);
            float vv[4] = {f.x, f.y, f.z, f.w};
#pragma unroll
            for (int j = 0; j < 4; j++) {
                uint32_t hb = f2tf32(vv[j]);
                float lo = vv[j] - __uint_as_float(hb);
                Wh_s[k * BSTR + c4 * 4 + j] = __uint_as_float(hb);
                Wl_s[k * BSTR + c4 * 4 + j] = __uint_as_float(f2tf32(lo));
            }
        }
        __syncthreads();

#pragma unroll
        for (int ks = 0; ks < 2; ks++) {     // two k8-steps per BK=16
            const int kb = ks * 8;
            uint32_t ah[2][4], al[2][4];
#pragma unroll
            for (int mt = 0; mt < 2; mt++) {
                int r = wrow * 32 + mt * 16 + rg;
                int k = kb + qt;
                ah[mt][0] = __float_as_uint(Ah_s[r * ASTR + k]);
                ah[mt][1] = __float_as_uint(Ah_s[(r + 8) * ASTR + k]);
                ah[mt][2] = __float_as_uint(Ah_s[r * ASTR + k + 4]);
                ah[mt][3] = __float_as_uint(Ah_s[(r + 8) * ASTR + k + 4]);
                al[mt][0] = __float_as_uint(Al_s[r * ASTR + k]);
                al[mt][1] = __float_as_uint(Al_s[(r + 8) * ASTR + k]);
                al[mt][2] = __float_as_uint(Al_s[r * ASTR + k + 4]);
                al[mt][3] = __float_as_uint(Al_s[(r + 8) * ASTR + k + 4]);
            }
            uint32_t bh[4][2], bl[4][2];
#pragma unroll
            for (int nt = 0; nt < 4; nt++) {
                int c = wcol * 32 + nt * 8 + rg;
                int k = kb + qt;
                bh[nt][0] = __float_as_uint(Wh_s[k * BSTR + c]);
                bh[nt][1] = __float_as_uint(Wh_s[(k + 4) * BSTR + c]);
                bl[nt][0] = __float_as_uint(Wl_s[k * BSTR + c]);
                bl[nt][1] = __float_as_uint(Wl_s[(k + 4) * BSTR + c]);
            }
#pragma unroll
            for (int mt = 0; mt < 2; mt++)
#pragma unroll
                for (int nt = 0; nt < 4; nt++) {
                    float* c = acc[mt][nt];
                    mma_tf32(c[0], c[1], c[2], c[3],
                             al[mt][0], al[mt][1], al[mt][2], al[mt][3],
                             bh[nt][0], bh[nt][1]);
                    mma_tf32(c[0], c[1], c[2], c[3],
                             ah[mt][0], ah[mt][1], ah[mt][2], ah[mt][3],
                             bl[nt][0], bl[nt][1]);
                    mma_tf32(c[0], c[1], c[2], c[3],
                             ah[mt][0], ah[mt][1], ah[mt][2], ah[mt][3],
                             bh[nt][0], bh[nt][1]);
                }
        }
        __syncthreads();
    }

    // ---- epilogue: store C + fused attention logits (head = col/8) ----
#pragma unroll
    for (int mt = 0; mt < 2; mt++)
#pragma unroll
        for (int nt = 0; nt < 4; nt++) {
            float* c = acc[mt][nt];
            int r0 = row0 + wrow * 32 + mt * 16 + rg;
            int r1 = r0 + 8;
            int col = wcol * 32 + nt * 8 + qt * 2;
            if (r0 < M)
                *reinterpret_cast<float2*>(&C[(size_t)r0 * 64 + col]) = make_float2(c[0], c[1]);
            if (r1 < M)
                *reinterpret_cast<float2*>(&C[(size_t)r1 * 64 + col]) = make_float2(c[2], c[3]);
            // logits: dot over this head's 8 cols, spread across the 4 quad threads
            float s0 = __ldg(&att_s[col]), s1 = __ldg(&att_s[col + 1]);
            float d0 = __ldg(&att_d[col]), d1 = __ldg(&att_d[col + 1]);
            float as_a = c[0] * s0 + c[1] * s1;
            float ad_a = c[0] * d0 + c[1] * d1;
            float as_b = c[2] * s0 + c[3] * s1;
            float ad_b = c[2] * d0 + c[3] * d1;
            as_a += __shfl_xor_sync(0xffffffffu, as_a, 1);
            as_a += __shfl_xor_sync(0xffffffffu, as_a, 2);
            ad_a += __shfl_xor_sync(0xffffffffu, ad_a, 1);
            ad_a += __shfl_xor_sync(0xffffffffu, ad_a, 2);
            as_b += __shfl_xor_sync(0xffffffffu, as_b, 1);
            as_b += __shfl_xor_sync(0xffffffffu, as_b, 2);
            ad_b += __shfl_xor_sync(0xffffffffu, ad_b, 1);
            ad_b += __shfl_xor_sync(0xffffffffu, ad_b, 2);
            int head = wcol * 4 + nt;
            if (qt == 0) {
                if (r0 < M) { asrc[r0 * 8 + head] = as_a; adst[r0 * 8 + head] = ad_a; }
                if (r1 < M) { asrc[r1 * 8 + head] = as_b; adst[r1 * 8 + head] = ad_b; }
            }
        }
}

// =======================  layer-2 GEMM (SIMT, fused logits)  ================
template <int BCOLS, int TN, int KTILE>
__global__ void gemm2_kernel(const float* __restrict__ A, int M, int K,
                             const float* __restrict__ W, float* __restrict__ C,
                             const float* __restrict__ att_s, const float* __restrict__ att_d,
                             float* __restrict__ asrc, float* __restrict__ adst) {
    constexpr int BROWS = 256;
    constexpr int TM = 8;
    constexpr int TX = BCOLS / TN;                    // 8
    constexpr int NT = TX * (BROWS / TM);             // 256
    constexpr int PAD = 4;

    __shared__ float xT[KTILE][BROWS + PAD];
    __shared__ float wS[KTILE][BCOLS];
    __shared__ float sAs[BCOLS], sAd[BCOLS];

    const int tid = threadIdx.x;
    const int tx = tid % TX;
    const int ty = tid / TX;
    const int row0 = blockIdx.x * BROWS;

    if (tid < BCOLS) { sAs[tid] = att_s[tid]; sAd[tid] = att_d[tid]; }

    float acc[TM][TN];
#pragma unroll
    for (int i = 0; i < TM; i++)
#pragma unroll
        for (int j = 0; j < TN; j++) acc[i][j] = 0.0f;

    for (int kt = 0; kt < K; kt += KTILE) {
        constexpr int KV = KTILE / 4;
        constexpr int XV = BROWS * KV;
#pragma unroll
        for (int v = tid; v < XV; v += NT) {
            int r  = v / KV;
            int kv = v % KV;
            int grow = row0 + r;
            float4 f = make_float4(0.f, 0.f, 0.f, 0.f);
            if (grow < M)
                f = *reinterpret_cast<const float4*>(&A[(size_t)grow * K + kt + kv * 4]);
            xT[kv * 4 + 0][r] = f.x;
            xT[kv * 4 + 1][r] = f.y;
            xT[kv * 4 + 2][r] = f.z;
            xT[kv * 4 + 3][r] = f.w;
        }
        constexpr int WV = KTILE * BCOLS / 4;
#pragma unroll
        for (int v = tid; v < WV; v += NT) {
            int k = v / (BCOLS / 4);
            int c = v % (BCOLS / 4);
            *reinterpret_cast<float4*>(&wS[k][c * 4]) =
                *reinterpret_cast<const float4*>(&W[(size_t)(kt + k) * BCOLS + c * 4]);
        }
        __syncthreads();

#pragma unroll
        for (int k = 0; k < KTILE; k++) {
            float a[TM];
            *reinterpret_cast<float4*>(&a[0]) = *reinterpret_cast<float4*>(&xT[k][ty * TM]);
            *reinterpret_cast<float4*>(&a[4]) = *reinterpret_cast<float4*>(&xT[k][ty * TM + 4]);
            float b[TN];
#pragma unroll
            for (int j = 0; j < TN; j++) b[j] = wS[k][tx * TN + j];
#pragma unroll
            for (int i = 0; i < TM; i++)
#pragma unroll
                for (int j = 0; j < TN; j++) acc[i][j] = fmaf(a[i], b[j], acc[i][j]);
        }
        __syncthreads();
    }

#pragma unroll
    for (int i = 0; i < TM; i++) {
        int grow = row0 + ty * TM + i;
        if (grow < M) {
#pragma unroll
            for (int j = 0; j < TN; j++) C[(size_t)grow * BCOLS + tx * TN + j] = acc[i][j];
        }
        float as = 0.f, ad = 0.f;
#pragma unroll
        for (int j = 0; j < TN; j++) {
            as = fmaf(acc[i][j], sAs[tx * TN + j], as);
            ad = fmaf(acc[i][j], sAd[tx * TN + j], ad);
        }
#pragma unroll
        for (int off = 4; off; off >>= 1) {
            as += __shfl_xor_sync(0xffffffffu, as, off);
            ad += __shfl_xor_sync(0xffffffffu, ad, off);
        }
        if (tx == 0 && grow < M) { asrc[grow] = as; adst[grow] = ad; }
    }
}

// =======================  layer-1 aggregation (warp per dst)  ===============
__global__ void agg1_kernel(const float* __restrict__ b1, int n) {
    int node = (blockIdx.x * blockDim.x + threadIdx.x) >> 5;
    int lane = threadIdx.x & 31;
    if (node >= n) return;

    const int myh = lane & 7;
    const int grp = lane >> 3;
    const int h0 = lane >> 3;
    const int h1f = 4 + (lane >> 3);

    float adst_l = g_adst1[node * 8 + myh];
    float acc0 = 0.f, acc1 = 0.f, wsum = 0.f;

    int beg = g_rowstart[node], end = g_rowstart[node + 1];
    for (int base = beg; base < end; base += 32) {
        int cnt = min(32, end - base);
        int li = base + lane; if (li >= end) li = end - 1;
        int sl = g_srcs[li];
        int nch = (cnt + 3) >> 2;
        for (int c = 0; c < nch; c++) {
            int eslot = c * 4 + grp;
            int esrc = __shfl_sync(0xffffffffu, sl, eslot < cnt ? eslot : 0);
            float w = 0.f;
            if (eslot < cnt) {
                float a = g_asrc1[esrc * 8 + myh] + adst_l;
                a = a > 0.f ? a : 0.2f * a;
                w = __expf(a);
                wsum += w;
            }
            int dmax = min(4, cnt - c * 4);
#pragma unroll 4
            for (int dd = 0; dd < dmax; dd++) {
                int src = __shfl_sync(0xffffffffu, sl, c * 4 + dd);
                float w0 = __shfl_sync(0xffffffffu, w, dd * 8 + h0);
                float w1 = __shfl_sync(0xffffffffu, w, dd * 8 + h1f);
                const float* hp = &g_h1[(size_t)src * 64];
                acc0 = fmaf(w0, hp[lane],      acc0);
                acc1 = fmaf(w1, hp[32 + lane], acc1);
            }
        }
    }
    wsum += __shfl_xor_sync(0xffffffffu, wsum, 8);
    wsum += __shfl_xor_sync(0xffffffffu, wsum, 16);
    {
        float a = g_asrc1[node * 8 + myh] + adst_l;
        a = a > 0.f ? a : 0.2f * a;
        float wself = __expf(a);
        wsum += wself;
        float w0 = __shfl_sync(0xffffffffu, wself, h0);
        float w1 = __shfl_sync(0xffffffffu, wself, h1f);
        const float* hp = &g_h1[(size_t)node * 64];
        acc0 = fmaf(w0, hp[lane],      acc0);
        acc1 = fmaf(w1, hp[32 + lane], acc1);
    }
    float s0 = __shfl_sync(0xffffffffu, wsum, h0);
    float s1 = __shfl_sync(0xffffffffu, wsum, h1f);
    float t0 = acc0 / (s0 + 1e-16f) + b1[lane];
    float t1 = acc1 / (s1 + 1e-16f) + b1[32 + lane];
    t0 = t0 > 0.f ? t0 : expm1f(t0);
    t1 = t1 > 0.f ? t1 : expm1f(t1);
    g_hf1[(size_t)node * 64 + lane]      = t0;
    g_hf1[(size_t)node * 64 + 32 + lane] = t1;
}

// =======================  layer-2 aggregation + log_softmax  ================
__global__ void agg2_kernel(const float* __restrict__ b2, float* __restrict__ out, int n) {
    int node = (blockIdx.x * blockDim.x + threadIdx.x) >> 5;
    int lane = threadIdx.x & 31;
    if (node >= n) return;

    float adst = g_adst2[node];
    float acc0 = 0.f, acc1 = 0.f, ssum = 0.f;

    int beg = g_rowstart[node], end = g_rowstart[node + 1];
    for (int base = beg; base < end; base += 32) {
        int cnt = min(32, end - base);
        int sl = 0;
        float wl = 0.f;
        if (base + lane < end) {
            sl = g_srcs[base + lane];
            float a = g_asrc2[sl] + adst;
            a = a > 0.f ? a : 0.2f * a;
            wl = __expf(a);
            ssum += wl;
        }
        for (int d = 0; d < cnt; d++) {
            int src = __shfl_sync(0xffffffffu, sl, d);
            float w  = __shfl_sync(0xffffffffu, wl, d);
            acc0 = fmaf(w, g_h2[(size_t)src * 40 + lane], acc0);
            if (lane < 8)
                acc1 = fmaf(w, g_h2[(size_t)src * 40 + 32 + lane], acc1);
        }
    }
#pragma unroll
    for (int o = 16; o; o >>= 1) ssum += __shfl_xor_sync(0xffffffffu, ssum, o);
    {
        float a = g_asrc2[node] + adst;
        a = a > 0.f ? a : 0.2f * a;
        float w = __expf(a);
        ssum += w;
        acc0 = fmaf(w, g_h2[(size_t)node * 40 + lane], acc0);
        if (lane < 8)
            acc1 = fmaf(w, g_h2[(size_t)node * 40 + 32 + lane], acc1);
    }
    float inv = 1.f / (ssum + 1e-16f);
    float v0 = acc0 * inv + b2[lane];
    float v1 = (lane < 8) ? acc1 * inv + b2[32 + lane] : -3.4e38f;

    float m = fmaxf(v0, v1);
#pragma unroll
    for (int o = 16; o; o >>= 1) m = fmaxf(m, __shfl_xor_sync(0xffffffffu, m, o));
    float es = expf(v0 - m) + (lane < 8 ? expf(v1 - m) : 0.f);
#pragma unroll
    for (int o = 16; o; o >>= 1) es += __shfl_xor_sync(0xffffffffu, es, o);
    float lse = m + logf(es);

    float* dr = &out[(size_t)node * 40];
    dr[lane] = v0 - lse;
    if (lane < 8) dr[32 + lane] = v1 - lse;
}

// ---------------- launch -----------------------------------------------------
static inline int cdiv(int a, int b) { return (a + b - 1) / b; }

extern "C" void kernel_launch(void* const* d_in, const int* in_sizes, int n_in,
                              void* d_out, int out_size) {
    const float* x   = (const float*)d_in[0];
    const int*   ei  = (const int*)d_in[1];
    const float* W1  = (const float*)d_in[2];
    const float* as1 = (const float*)d_in[3];
    const float* ad1 = (const float*)d_in[4];
    const float* b1  = (const float*)d_in[5];
    const float* W2  = (const float*)d_in[6];
    const float* as2 = (const float*)d_in[7];
    const float* ad2 = (const float*)d_in[8];
    const float* b2  = (const float*)d_in[9];
    float*       out = (float*)d_out;

    const int n = in_sizes[0] / 512;      // 100000
    const int E = in_sizes[1] / 2;        // 1600000

    float *p_h1, *p_hf1, *p_h2, *p_as1, *p_ad1, *p_as2, *p_ad2;
    void* p_counts;
    cudaGetSymbolAddress((void**)&p_h1,  g_h1);
    cudaGetSymbolAddress((void**)&p_hf1, g_hf1);
    cudaGetSymbolAddress((void**)&p_h2,  g_h2);
    cudaGetSymbolAddress((void**)&p_as1, g_asrc1);
    cudaGetSymbolAddress((void**)&p_ad1, g_adst1);
    cudaGetSymbolAddress((void**)&p_as2, g_asrc2);
    cudaGetSymbolAddress((void**)&p_ad2, g_adst2);
    cudaGetSymbolAddress(&p_counts, g_counts);

    static cudaStream_t s1 = nullptr;
    static cudaEvent_t ev_fork = nullptr, ev_join = nullptr;
    if (s1 == nullptr) {
        cudaStreamCreateWithFlags(&s1, cudaStreamNonBlocking);
        cudaEventCreateWithFlags(&ev_fork, cudaEventDisableTiming);
        cudaEventCreateWithFlags(&ev_join, cudaEventDisableTiming);
    }

    const int nb_scan = cdiv(n, 1024);

    // ---- fork: CSR build on s1, concurrent with gemm1 on default stream ----
    cudaEventRecord(ev_fork, 0);
    cudaStreamWaitEvent(s1, ev_fork, 0);

    cudaMemsetAsync(p_counts, 0, n * sizeof(int), s1);
    hist_kernel<<<cdiv(E, 256), 256, 0, s1>>>(ei, E);
    scan_part1<<<nb_scan, 1024, 0, s1>>>(n);
    scan_part2<<<1, 32, 0, s1>>>(nb_scan, n, E);
    scan_part3<<<nb_scan, 1024, 0, s1>>>(n);
    scatter_kernel<<<cdiv(E, 256), 256, 0, s1>>>(ei, E);
    cudaEventRecord(ev_join, s1);

    // ---- layer-1 GEMM: tf32 tensor cores (overlaps CSR build) ----
    gemm1_tf32<<<cdiv(n, 128), 256>>>(x, n, W1, p_h1, as1, ad1, p_as1, p_ad1);

    // ---- join, then aggregation + layer 2 ----
    cudaStreamWaitEvent(0, ev_join, 0);
    agg1_kernel<<<cdiv(n * 32, 256), 256>>>(b1, n);
    gemm2_kernel<40, 5, 32><<<cdiv(n, 256), 256>>>(p_hf1, n, 64, W2, p_h2,
                                                   as2, ad2, p_as2, p_ad2);
    agg2_kernel<<<cdiv(n * 32, 256), 256>>>(b2, out, n);
}

// round 7
// speedup vs baseline: 1.7314x; 1.0083x over previous
#include <cuda_runtime.h>
#include <math.h>
#include <stdint.h>

#define NMAX 100000
#define EMAX 1600000

// ---------------- scratch (static __device__, per harness rules) -------------
__device__ float g_h1[NMAX * 64];
__device__ float g_asrc1[NMAX * 8];
__device__ float g_adst1[NMAX * 8];
__device__ float g_hf1[NMAX * 64];
__device__ float g_h2[NMAX * 40];
__device__ float g_asrc2[NMAX];
__device__ float g_adst2[NMAX];

__device__ int g_counts[NMAX];
__device__ int g_cursor[NMAX];
__device__ int g_bsum[256];
__device__ int g_rowstart[NMAX + 1];
__device__ int g_srcs[EMAX];

// =======================  CSR build  ========================================

__global__ void hist_kernel(const int* __restrict__ ei, int E) {
    int e = blockIdx.x * blockDim.x + threadIdx.x;
    if (e >= E) return;
    atomicAdd(&g_counts[ei[E + e]], 1);
}

__global__ void scan_part1(int n) {
    __shared__ int sh[1024];
    int i = blockIdx.x * 1024 + threadIdx.x;
    sh[threadIdx.x] = (i < n) ? g_counts[i] : 0;
    __syncthreads();
#pragma unroll
    for (int off = 512; off; off >>= 1) {
        if (threadIdx.x < off) sh[threadIdx.x] += sh[threadIdx.x + off];
        __syncthreads();
    }
    if (threadIdx.x == 0) g_bsum[blockIdx.x] = sh[0];
}

// fused: per-block prefix of block sums + intra-block exclusive scan
__global__ void scan_part23(int nb, int n, int E) {
    __shared__ int sh[1024];
    __shared__ int soff;
    int t = threadIdx.x;
    int b = blockIdx.x;
    if (t < 32) {
        int acc = 0;
        for (int i = t; i < b; i += 32) acc += g_bsum[i];
#pragma unroll
        for (int o = 16; o; o >>= 1) acc += __shfl_xor_sync(0xffffffffu, acc, o);
        if (t == 0) soff = acc;
    }
    int i = b * 1024 + t;
    int v = (i < n) ? g_counts[i] : 0;
    sh[t] = v;
    __syncthreads();
#pragma unroll
    for (int off = 1; off < 1024; off <<= 1) {
        int add = (t >= off) ? sh[t - off] : 0;
        __syncthreads();
        sh[t] += add;
        __syncthreads();
    }
    if (i < n) {
        int ex = sh[t] - v + soff;
        g_rowstart[i] = ex;
        g_cursor[i]   = ex;
    }
    if (b == nb - 1 && t == 0) g_rowstart[n] = E;
}

__global__ void scatter_kernel(const int* __restrict__ ei, int E) {
    int e = blockIdx.x * blockDim.x + threadIdx.x;
    if (e >= E) return;
    int src = ei[e];
    int dst = ei[E + e];
    int pos = atomicAdd(&g_cursor[dst], 1);
    g_srcs[pos] = src;
}

// =======================  tf32 helpers  =====================================

__device__ __forceinline__ uint32_t f2tf32(float v) {
    uint32_t r;
    asm("cvt.rna.tf32.f32 %0, %1;" : "=r"(r) : "f"(v));
    return r;
}

__device__ __forceinline__ void mma_tf32(float& c0, float& c1, float& c2, float& c3,
                                         uint32_t a0, uint32_t a1, uint32_t a2, uint32_t a3,
                                         uint32_t b0, uint32_t b1) {
    asm volatile("mma.sync.aligned.m16n8k8.row.col.f32.tf32.tf32.f32 "
                 "{%0,%1,%2,%3}, {%4,%5,%6,%7}, {%8,%9}, {%0,%1,%2,%3};"
                 : "+f"(c0), "+f"(c1), "+f"(c2), "+f"(c3)
                 : "r"(a0), "r"(a1), "r"(a2), "r"(a3), "r"(b0), "r"(b1));
}

// =======================  layer-1 GEMM: tf32 3-pass MMA  ====================
__global__ __launch_bounds__(256, 2)
void gemm1_tf32(const float* __restrict__ A, int M,
                const float* __restrict__ W, float* __restrict__ C,
                const float* __restrict__ att_s, const float* __restrict__ att_d,
                float* __restrict__ asrc, float* __restrict__ adst) {
    constexpr int BM = 128, BN = 64, BK = 16;
    constexpr int ASTR = BK + 4;   // 20
    constexpr int BSTR = BN + 8;   // 72

    __shared__ float Ah_s[BM * ASTR], Al_s[BM * ASTR];
    __shared__ float Wh_s[BK * BSTR], Wl_s[BK * BSTR];

    const int tid  = threadIdx.x;
    const int lane = tid & 31;
    const int warp = tid >> 5;
    const int wrow = warp >> 1;
    const int wcol = warp & 1;
    const int row0 = blockIdx.x * BM;
    const int qt   = lane & 3;
    const int rg   = lane >> 2;

    float acc[2][4][4];
#pragma unroll
    for (int mt = 0; mt < 2; mt++)
#pragma unroll
        for (int nt = 0; nt < 4; nt++)
#pragma unroll
            for (int r = 0; r < 4; r++) acc[mt][nt][r] = 0.f;

    for (int kt = 0; kt < 512; kt += BK) {
#pragma unroll
        for (int i = 0; i < 2; i++) {
            int idx = tid + i * 256;
            int row = idx >> 2;
            int kq  = idx & 3;
            float4 f = make_float4(0.f, 0.f, 0.f, 0.f);
            int grow = row0 + row;
            if (grow < M)
                f = *reinterpret_cast<const float4*>(&A[(size_t)grow * 512 + kt + kq * 4]);
            float vv[4] = {f.x, f.y, f.z, f.w};
#pragma unroll
            for (int j = 0; j < 4; j++) {
                uint32_t hb = f2tf32(vv[j]);
                float lo = vv[j] - __uint_as_float(hb);
                Ah_s[row * ASTR + kq * 4 + j] = __uint_as_float(hb);
                Al_s[row * ASTR + kq * 4 + j] = __uint_as_float(f2tf32(lo));
            }
        }
        {
            int k  = tid >> 4;
            int c4 = tid & 15;
            float4 f = *reinterpret_cast<const float4*>(&W[(size_t)(kt + k) * 64 + c4 * 4]);
            float vv[4] = {f.x, f.y, f.z, f.w};
#pragma unroll
            for (int j = 0; j < 4; j++) {
                uint32_t hb = f2tf32(vv[j]);
                float lo = vv[j] - __uint_as_float(hb);
                Wh_s[k * BSTR + c4 * 4 + j] = __uint_as_float(hb);
                Wl_s[k * BSTR + c4 * 4 + j] = __uint_as_float(f2tf32(lo));
            }
        }
        __syncthreads();

#pragma unroll
        for (int ks = 0; ks < 2; ks++) {
            const int kb = ks * 8;
            uint32_t ah[2][4], al[2][4];
#pragma unroll
            for (int mt = 0; mt < 2; mt++) {
                int r = wrow * 32 + mt * 16 + rg;
                int k = kb + qt;
                ah[mt][0] = __float_as_uint(Ah_s[r * ASTR + k]);
                ah[mt][1] = __float_as_uint(Ah_s[(r + 8) * ASTR + k]);
                ah[mt][2] = __float_as_uint(Ah_s[r * ASTR + k + 4]);
                ah[mt][3] = __float_as_uint(Ah_s[(r + 8) * ASTR + k + 4]);
                al[mt][0] = __float_as_uint(Al_s[r * ASTR + k]);
                al[mt][1] = __float_as_uint(Al_s[(r + 8) * ASTR + k]);
                al[mt][2] = __float_as_uint(Al_s[r * ASTR + k + 4]);
                al[mt][3] = __float_as_uint(Al_s[(r + 8) * ASTR + k + 4]);
            }
            uint32_t bh[4][2], bl[4][2];
#pragma unroll
            for (int nt = 0; nt < 4; nt++) {
                int c = wcol * 32 + nt * 8 + rg;
                int k = kb + qt;
                bh[nt][0] = __float_as_uint(Wh_s[k * BSTR + c]);
                bh[nt][1] = __float_as_uint(Wh_s[(k + 4) * BSTR + c]);
                bl[nt][0] = __float_as_uint(Wl_s[k * BSTR + c]);
                bl[nt][1] = __float_as_uint(Wl_s[(k + 4) * BSTR + c]);
            }
#pragma unroll
            for (int mt = 0; mt < 2; mt++)
#pragma unroll
                for (int nt = 0; nt < 4; nt++) {
                    float* c = acc[mt][nt];
                    mma_tf32(c[0], c[1], c[2], c[3],
                             al[mt][0], al[mt][1], al[mt][2], al[mt][3],
                             bh[nt][0], bh[nt][1]);
                    mma_tf32(c[0], c[1], c[2], c[3],
                             ah[mt][0], ah[mt][1], ah[mt][2], ah[mt][3],
                             bl[nt][0], bl[nt][1]);
                    mma_tf32(c[0], c[1], c[2], c[3],
                             ah[mt][0], ah[mt][1], ah[mt][2], ah[mt][3],
                             bh[nt][0], bh[nt][1]);
                }
        }
        __syncthreads();
    }

#pragma unroll
    for (int mt = 0; mt < 2; mt++)
#pragma unroll
        for (int nt = 0; nt < 4; nt++) {
            float* c = acc[mt][nt];
            int r0 = row0 + wrow * 32 + mt * 16 + rg;
            int r1 = r0 + 8;
            int col = wcol * 32 + nt * 8 + qt * 2;
            if (r0 < M)
                *reinterpret_cast<float2*>(&C[(size_t)r0 * 64 + col]) = make_float2(c[0], c[1]);
            if (r1 < M)
                *reinterpret_cast<float2*>(&C[(size_t)r1 * 64 + col]) = make_float2(c[2], c[3]);
            float s0 = __ldg(&att_s[col]), s1 = __ldg(&att_s[col + 1]);
            float d0 = __ldg(&att_d[col]), d1 = __ldg(&att_d[col + 1]);
            float as_a = c[0] * s0 + c[1] * s1;
            float ad_a = c[0] * d0 + c[1] * d1;
            float as_b = c[2] * s0 + c[3] * s1;
            float ad_b = c[2] * d0 + c[3] * d1;
            as_a += __shfl_xor_sync(0xffffffffu, as_a, 1);
            as_a += __shfl_xor_sync(0xffffffffu, as_a, 2);
            ad_a += __shfl_xor_sync(0xffffffffu, ad_a, 1);
            ad_a += __shfl_xor_sync(0xffffffffu, ad_a, 2);
            as_b += __shfl_xor_sync(0xffffffffu, as_b, 1);
            as_b += __shfl_xor_sync(0xffffffffu, as_b, 2);
            ad_b += __shfl_xor_sync(0xffffffffu, ad_b, 1);
            ad_b += __shfl_xor_sync(0xffffffffu, ad_b, 2);
            int head = wcol * 4 + nt;
            if (qt == 0) {
                if (r0 < M) { asrc[r0 * 8 + head] = as_a; adst[r0 * 8 + head] = ad_a; }
                if (r1 < M) { asrc[r1 * 8 + head] = as_b; adst[r1 * 8 + head] = ad_b; }
            }
        }
}

// =======================  layer-2 GEMM (SIMT, fused logits)  ================
// Operates on a row range via pre-offset pointers (row-independent).
template <int BCOLS, int TN, int KTILE>
__global__ void gemm2_kernel(const float* __restrict__ A, int M, int K,
                             const float* __restrict__ W, float* __restrict__ C,
                             const float* __restrict__ att_s, const float* __restrict__ att_d,
                             float* __restrict__ asrc, float* __restrict__ adst) {
    constexpr int BROWS = 256;
    constexpr int TM = 8;
    constexpr int TX = BCOLS / TN;
    constexpr int NT = TX * (BROWS / TM);
    constexpr int PAD = 4;

    __shared__ float xT[KTILE][BROWS + PAD];
    __shared__ float wS[KTILE][BCOLS];
    __shared__ float sAs[BCOLS], sAd[BCOLS];

    const int tid = threadIdx.x;
    const int tx = tid % TX;
    const int ty = tid / TX;
    const int row0 = blockIdx.x * BROWS;

    if (tid < BCOLS) { sAs[tid] = att_s[tid]; sAd[tid] = att_d[tid]; }

    float acc[TM][TN];
#pragma unroll
    for (int i = 0; i < TM; i++)
#pragma unroll
        for (int j = 0; j < TN; j++) acc[i][j] = 0.0f;

    for (int kt = 0; kt < K; kt += KTILE) {
        constexpr int KV = KTILE / 4;
        constexpr int XV = BROWS * KV;
#pragma unroll
        for (int v = tid; v < XV; v += NT) {
            int r  = v / KV;
            int kv = v % KV;
            int grow = row0 + r;
            float4 f = make_float4(0.f, 0.f, 0.f, 0.f);
            if (grow < M)
                f = *reinterpret_cast<const float4*>(&A[(size_t)grow * K + kt + kv * 4]);
            xT[kv * 4 + 0][r] = f.x;
            xT[kv * 4 + 1][r] = f.y;
            xT[kv * 4 + 2][r] = f.z;
            xT[kv * 4 + 3][r] = f.w;
        }
        constexpr int WV = KTILE * BCOLS / 4;
#pragma unroll
        for (int v = tid; v < WV; v += NT) {
            int k = v / (BCOLS / 4);
            int c = v % (BCOLS / 4);
            *reinterpret_cast<float4*>(&wS[k][c * 4]) =
                *reinterpret_cast<const float4*>(&W[(size_t)(kt + k) * BCOLS + c * 4]);
        }
        __syncthreads();

#pragma unroll
        for (int k = 0; k < KTILE; k++) {
            float a[TM];
            *reinterpret_cast<float4*>(&a[0]) = *reinterpret_cast<float4*>(&xT[k][ty * TM]);
            *reinterpret_cast<float4*>(&a[4]) = *reinterpret_cast<float4*>(&xT[k][ty * TM + 4]);
            float b[TN];
#pragma unroll
            for (int j = 0; j < TN; j++) b[j] = wS[k][tx * TN + j];
#pragma unroll
            for (int i = 0; i < TM; i++)
#pragma unroll
                for (int j = 0; j < TN; j++) acc[i][j] = fmaf(a[i], b[j], acc[i][j]);
        }
        __syncthreads();
    }

#pragma unroll
    for (int i = 0; i < TM; i++) {
        int grow = row0 + ty * TM + i;
        if (grow < M) {
#pragma unroll
            for (int j = 0; j < TN; j++) C[(size_t)grow * BCOLS + tx * TN + j] = acc[i][j];
        }
        float as = 0.f, ad = 0.f;
#pragma unroll
        for (int j = 0; j < TN; j++) {
            as = fmaf(acc[i][j], sAs[tx * TN + j], as);
            ad = fmaf(acc[i][j], sAd[tx * TN + j], ad);
        }
#pragma unroll
        for (int off = 4; off; off >>= 1) {
            as += __shfl_xor_sync(0xffffffffu, as, off);
            ad += __shfl_xor_sync(0xffffffffu, ad, off);
        }
        if (tx == 0 && grow < M) { asrc[grow] = as; adst[grow] = ad; }
    }
}

// =======================  layer-1 aggregation (warp per dst)  ===============
// Weight phase stages all 32 edge-weights (8 heads each by lane) into smem,
// then the accumulation loop reads them via conflict-free broadcast LDS.
__global__ void agg1_kernel(const float* __restrict__ b1, int node0, int node1) {
    __shared__ float wsm[8][32][8];
    const int wid  = threadIdx.x >> 5;
    const int lane = threadIdx.x & 31;
    int node = node0 + ((blockIdx.x * blockDim.x + threadIdx.x) >> 5);
    if (node >= node1) return;

    const int myh = lane & 7;
    const int grp = lane >> 3;
    const int h0  = lane >> 3;
    const int h1f = 4 + h0;

    float adst_l = g_adst1[node * 8 + myh];
    float acc0 = 0.f, acc1 = 0.f, wsum = 0.f;

    int beg = g_rowstart[node], end = g_rowstart[node + 1];
    for (int base = beg; base < end; base += 32) {
        int cnt = min(32, end - base);
        int li = base + lane; if (li >= end) li = end - 1;
        int sl = g_srcs[li];

        // ---- weight phase: lane (grp,myh) covers edge slots grp, grp+4, ... ----
#pragma unroll
        for (int c = 0; c < 8; c++) {
            int eslot = c * 4 + grp;
            int esrc = __shfl_sync(0xffffffffu, sl, eslot);
            if (eslot < cnt) {
                float a = g_asrc1[esrc * 8 + myh] + adst_l;
                a = a > 0.f ? a : 0.2f * a;
                float w = __expf(a);
                wsum += w;
                wsm[wid][eslot][myh] = w;
            }
        }
        __syncwarp();

        // ---- accumulation: broadcast LDS weights (no exp/gather dependency) ----
#pragma unroll 4
        for (int d = 0; d < cnt; d++) {
            int src = __shfl_sync(0xffffffffu, sl, d);
            float w0 = wsm[wid][d][h0];
            float w1 = wsm[wid][d][h1f];
            const float* hp = &g_h1[(size_t)src * 64];
            acc0 = fmaf(w0, hp[lane],      acc0);
            acc1 = fmaf(w1, hp[32 + lane], acc1);
        }
        __syncwarp();
    }
    // reduce wsum over the 4 edge-slot replicas
    wsum += __shfl_xor_sync(0xffffffffu, wsum, 8);
    wsum += __shfl_xor_sync(0xffffffffu, wsum, 16);
    // self loop
    {
        float a = g_asrc1[node * 8 + myh] + adst_l;
        a = a > 0.f ? a : 0.2f * a;
        float wself = __expf(a);
        wsum += wself;
        float w0 = __shfl_sync(0xffffffffu, wself, h0);
        float w1 = __shfl_sync(0xffffffffu, wself, h1f);
        const float* hp = &g_h1[(size_t)node * 64];
        acc0 = fmaf(w0, hp[lane],      acc0);
        acc1 = fmaf(w1, hp[32 + lane], acc1);
    }
    float s0 = __shfl_sync(0xffffffffu, wsum, h0);
    float s1 = __shfl_sync(0xffffffffu, wsum, h1f);
    float t0 = acc0 / (s0 + 1e-16f) + b1[lane];
    float t1 = acc1 / (s1 + 1e-16f) + b1[32 + lane];
    t0 = t0 > 0.f ? t0 : expm1f(t0);
    t1 = t1 > 0.f ? t1 : expm1f(t1);
    g_hf1[(size_t)node * 64 + lane]      = t0;
    g_hf1[(size_t)node * 64 + 32 + lane] = t1;
}

// =======================  layer-2 aggregation + log_softmax  ================
__global__ void agg2_kernel(const float* __restrict__ b2, float* __restrict__ out, int n) {
    int node = (blockIdx.x * blockDim.x + threadIdx.x) >> 5;
    int lane = threadIdx.x & 31;
    if (node >= n) return;

    float adst = g_adst2[node];
    float acc0 = 0.f, acc1 = 0.f, ssum = 0.f;

    int beg = g_rowstart[node], end = g_rowstart[node + 1];
    for (int base = beg; base < end; base += 32) {
        int cnt = min(32, end - base);
        int sl = 0;
        float wl = 0.f;
        if (base + lane < end) {
            sl = g_srcs[base + lane];
            float a = g_asrc2[sl] + adst;
            a = a > 0.f ? a : 0.2f * a;
            wl = __expf(a);
            ssum += wl;
        }
#pragma unroll 4
        for (int d = 0; d < cnt; d++) {
            int src = __shfl_sync(0xffffffffu, sl, d);
            float w  = __shfl_sync(0xffffffffu, wl, d);
            acc0 = fmaf(w, g_h2[(size_t)src * 40 + lane], acc0);
            if (lane < 8)
                acc1 = fmaf(w, g_h2[(size_t)src * 40 + 32 + lane], acc1);
        }
    }
#pragma unroll
    for (int o = 16; o; o >>= 1) ssum += __shfl_xor_sync(0xffffffffu, ssum, o);
    {
        float a = g_asrc2[node] + adst;
        a = a > 0.f ? a : 0.2f * a;
        float w = __expf(a);
        ssum += w;
        acc0 = fmaf(w, g_h2[(size_t)node * 40 + lane], acc0);
        if (lane < 8)
            acc1 = fmaf(w, g_h2[(size_t)node * 40 + 32 + lane], acc1);
    }
    float inv = 1.f / (ssum + 1e-16f);
    float v0 = acc0 * inv + b2[lane];
    float v1 = (lane < 8) ? acc1 * inv + b2[32 + lane] : -3.4e38f;

    float m = fmaxf(v0, v1);
#pragma unroll
    for (int o = 16; o; o >>= 1) m = fmaxf(m, __shfl_xor_sync(0xffffffffu, m, o));
    float es = expf(v0 - m) + (lane < 8 ? expf(v1 - m) : 0.f);
#pragma unroll
    for (int o = 16; o; o >>= 1) es += __shfl_xor_sync(0xffffffffu, es, o);
    float lse = m + logf(es);

    float* dr = &out[(size_t)node * 40];
    dr[lane] = v0 - lse;
    if (lane < 8) dr[32 + lane] = v1 - lse;
}

// ---------------- launch -----------------------------------------------------
static inline int cdiv(int a, int b) { return (a + b - 1) / b; }

extern "C" void kernel_launch(void* const* d_in, const int* in_sizes, int n_in,
                              void* d_out, int out_size) {
    const float* x   = (const float*)d_in[0];
    const int*   ei  = (const int*)d_in[1];
    const float* W1  = (const float*)d_in[2];
    const float* as1 = (const float*)d_in[3];
    const float* ad1 = (const float*)d_in[4];
    const float* b1  = (const float*)d_in[5];
    const float* W2  = (const float*)d_in[6];
    const float* as2 = (const float*)d_in[7];
    const float* ad2 = (const float*)d_in[8];
    const float* b2  = (const float*)d_in[9];
    float*       out = (float*)d_out;

    const int n = in_sizes[0] / 512;      // 100000
    const int E = in_sizes[1] / 2;        // 1600000

    float *p_h1, *p_hf1, *p_h2, *p_as1, *p_ad1, *p_as2, *p_ad2;
    void* p_counts;
    cudaGetSymbolAddress((void**)&p_h1,  g_h1);
    cudaGetSymbolAddress((void**)&p_hf1, g_hf1);
    cudaGetSymbolAddress((void**)&p_h2,  g_h2);
    cudaGetSymbolAddress((void**)&p_as1, g_asrc1);
    cudaGetSymbolAddress((void**)&p_ad1, g_adst1);
    cudaGetSymbolAddress((void**)&p_as2, g_asrc2);
    cudaGetSymbolAddress((void**)&p_ad2, g_adst2);
    cudaGetSymbolAddress(&p_counts, g_counts);

    static cudaStream_t s1 = nullptr;
    static cudaEvent_t ev_fork = nullptr, ev_g1 = nullptr, ev_csr = nullptr, ev_b = nullptr;
    if (s1 == nullptr) {
        cudaStreamCreateWithFlags(&s1, cudaStreamNonBlocking);
        cudaEventCreateWithFlags(&ev_fork, cudaEventDisableTiming);
        cudaEventCreateWithFlags(&ev_g1,   cudaEventDisableTiming);
        cudaEventCreateWithFlags(&ev_csr,  cudaEventDisableTiming);
        cudaEventCreateWithFlags(&ev_b,    cudaEventDisableTiming);
    }

    const int nb_scan = cdiv(n, 1024);
    const int nA = ((n / 2) + 255) & ~255;      // A: [0,nA), B: [nA,n)
    const int nB = n - nA;

    // ---- fork: CSR build on s1 overlapping gemm1 on main -------------------
    cudaEventRecord(ev_fork, 0);
    cudaStreamWaitEvent(s1, ev_fork, 0);

    cudaMemsetAsync(p_counts, 0, n * sizeof(int), s1);
    hist_kernel <<<cdiv(E, 256), 256, 0, s1>>>(ei, E);              // kernel 1
    scan_part1  <<<nb_scan, 1024, 0, s1>>>(n);                      // kernel 2
    scan_part23 <<<nb_scan, 1024, 0, s1>>>(nb_scan, n, E);          // kernel 3

    gemm1_tf32<<<cdiv(n, 128), 256>>>(x, n, W1, p_h1,               // kernel 4 (profiled)
                                      as1, ad1, p_as1, p_ad1);
    cudaEventRecord(ev_g1, 0);

    scatter_kernel<<<cdiv(E, 256), 256, 0, s1>>>(ei, E);            // kernel 5
    cudaEventRecord(ev_csr, s1);

    // ---- B half on s1 (needs gemm1 + CSR), overlaps A half on main ---------
    cudaStreamWaitEvent(s1, ev_g1, 0);
    agg1_kernel<<<cdiv(nB * 32, 256), 256, 0, s1>>>(b1, nA, n);     // kernel 6
    gemm2_kernel<40, 5, 32><<<cdiv(nB, 256), 256, 0, s1>>>(         // kernel 7
        p_hf1 + (size_t)nA * 64, nB, 64, W2, p_h2 + (size_t)nA * 40,
        as2, ad2, p_as2 + nA, p_ad2 + nA);
    cudaEventRecord(ev_b, s1);

    // ---- A half + final on main --------------------------------------------
    cudaStreamWaitEvent(0, ev_csr, 0);
    agg1_kernel<<<cdiv(nA * 32, 256), 256>>>(b1, 0, nA);            // kernel 8
    gemm2_kernel<40, 5, 32><<<cdiv(nA, 256), 256>>>(                // kernel 9
        p_hf1, nA, 64, W2, p_h2, as2, ad2, p_as2, p_ad2);

    cudaStreamWaitEvent(0, ev_b, 0);
    agg2_kernel<<<cdiv(n * 32, 256), 256>>>(b2, out, n);            // kernel 10
}

// round 8
// speedup vs baseline: 1.9785x; 1.1427x over previous
#include <cuda_runtime.h>
#include <cuda_bf16.h>
#include <math.h>
#include <stdint.h>

#define NMAX 100000
#define EMAX 1600000

// ---------------- scratch (static __device__, per harness rules) -------------
__device__ float g_h1[NMAX * 64];
__device__ float g_asrc1[NMAX * 8];
__device__ float g_adst1[NMAX * 8];
__device__ float g_hf1[NMAX * 64];
__device__ float g_h2[NMAX * 40];
__device__ float g_asrc2[NMAX];
__device__ float g_adst2[NMAX];

__device__ int g_counts[NMAX];
__device__ int g_cursor[NMAX];
__device__ int g_bsum[256];
__device__ int g_rowstart[NMAX + 1];
__device__ int g_srcs[EMAX];

// =======================  CSR build  ========================================

__global__ void hist_kernel(const int* __restrict__ ei, int E) {
    int e = blockIdx.x * blockDim.x + threadIdx.x;
    if (e >= E) return;
    atomicAdd(&g_counts[ei[E + e]], 1);
}

__global__ void scan_part1(int n) {
    __shared__ int sh[1024];
    int i = blockIdx.x * 1024 + threadIdx.x;
    sh[threadIdx.x] = (i < n) ? g_counts[i] : 0;
    __syncthreads();
#pragma unroll
    for (int off = 512; off; off >>= 1) {
        if (threadIdx.x < off) sh[threadIdx.x] += sh[threadIdx.x + off];
        __syncthreads();
    }
    if (threadIdx.x == 0) g_bsum[blockIdx.x] = sh[0];
}

__global__ void scan_part23(int nb, int n, int E) {
    __shared__ int sh[1024];
    __shared__ int soff;
    int t = threadIdx.x;
    int b = blockIdx.x;
    if (t < 32) {
        int acc = 0;
        for (int i = t; i < b; i += 32) acc += g_bsum[i];
#pragma unroll
        for (int o = 16; o; o >>= 1) acc += __shfl_xor_sync(0xffffffffu, acc, o);
        if (t == 0) soff = acc;
    }
    int i = b * 1024 + t;
    int v = (i < n) ? g_counts[i] : 0;
    sh[t] = v;
    __syncthreads();
#pragma unroll
    for (int off = 1; off < 1024; off <<= 1) {
        int add = (t >= off) ? sh[t - off] : 0;
        __syncthreads();
        sh[t] += add;
        __syncthreads();
    }
    if (i < n) {
        int ex = sh[t] - v + soff;
        g_rowstart[i] = ex;
        g_cursor[i]   = ex;
    }
    if (b == nb - 1 && t == 0) g_rowstart[n] = E;
}

__global__ void scatter_kernel(const int* __restrict__ ei, int E) {
    int e = blockIdx.x * blockDim.x + threadIdx.x;
    if (e >= E) return;
    int src = ei[e];
    int dst = ei[E + e];
    int pos = atomicAdd(&g_cursor[dst], 1);
    g_srcs[pos] = src;
}

// =======================  bf16 split helpers  ================================

__device__ __forceinline__ void mma_bf16(float& c0, float& c1, float& c2, float& c3,
                                         uint32_t a0, uint32_t a1, uint32_t a2, uint32_t a3,
                                         uint32_t b0, uint32_t b1) {
    asm volatile("mma.sync.aligned.m16n8k16.row.col.f32.bf16.bf16.f32 "
                 "{%0,%1,%2,%3}, {%4,%5,%6,%7}, {%8,%9}, {%0,%1,%2,%3};"
                 : "+f"(c0), "+f"(c1), "+f"(c2), "+f"(c3)
                 : "r"(a0), "r"(a1), "r"(a2), "r"(a3), "r"(b0), "r"(b1));
}

__device__ __forceinline__ void split_bf16(float v, __nv_bfloat16& hi, __nv_bfloat16& lo) {
    hi = __float2bfloat16(v);
    lo = __float2bfloat16(v - __bfloat162float(hi));
}

// =======================  layer-1 GEMM: bf16 3-pass MMA  ====================
// C[M,64] = A[M,512] @ W[512,64] via (Ah+Al)(Wh+Wl) ~= AhWh + AlWh + AhWl.
// Block 128x64, 8 warps (4x2), warp tile 32x32, mma m16n8k16.
// Fragments: 2 bf16/register -> LDS.32 loads, conflict-free (stride 40 bf16).
__global__ __launch_bounds__(256, 2)
void gemm1_bf16(const float* __restrict__ A, int M,
                const float* __restrict__ W, float* __restrict__ C,
                const float* __restrict__ att_s, const float* __restrict__ att_d,
                float* __restrict__ asrc, float* __restrict__ adst) {
    constexpr int BM = 128, BN = 64, BK = 32;
    constexpr int AS = BK + 8;                 // 40 bf16 row stride (80B = 20 banks)

    __shared__ __nv_bfloat16 Ah_s[BM][AS], Al_s[BM][AS];
    __shared__ __nv_bfloat16 Bh_s[BN][AS], Bl_s[BN][AS];   // [n][k]

    const int tid  = threadIdx.x;
    const int lane = tid & 31;
    const int warp = tid >> 5;
    const int wrow = warp >> 1;
    const int wcol = warp & 1;
    const int row0 = blockIdx.x * BM;
    const int qt   = lane & 3;
    const int rg   = lane >> 2;

    float acc[2][4][4];
#pragma unroll
    for (int mt = 0; mt < 2; mt++)
#pragma unroll
        for (int nt = 0; nt < 4; nt++)
#pragma unroll
            for (int r = 0; r < 4; r++) acc[mt][nt][r] = 0.f;

    const int arow = tid >> 1;
    const int kh   = (tid & 1) * 16;

    for (int kt = 0; kt < 512; kt += BK) {
        // ---- stage A: 16 consecutive k-floats per thread -> hi/lo bf16 ----
        {
            int grow = row0 + arow;
#pragma unroll
            for (int q = 0; q < 4; q++) {
                float4 f = make_float4(0.f, 0.f, 0.f, 0.f);
                if (grow < M)
                    f = *reinterpret_cast<const float4*>(&A[(size_t)grow * 512 + kt + kh + q * 4]);
                float vv[4] = {f.x, f.y, f.z, f.w};
                __nv_bfloat16 h[4], l[4];
#pragma unroll
                for (int j = 0; j < 4; j++) split_bf16(vv[j], h[j], l[j]);
                // pack pairs -> STS.32
                *reinterpret_cast<uint32_t*>(&Ah_s[arow][kh + q * 4])     =
                    (uint32_t)__bfloat16_as_ushort(h[0]) | ((uint32_t)__bfloat16_as_ushort(h[1]) << 16);
                *reinterpret_cast<uint32_t*>(&Ah_s[arow][kh + q * 4 + 2]) =
                    (uint32_t)__bfloat16_as_ushort(h[2]) | ((uint32_t)__bfloat16_as_ushort(h[3]) << 16);
                *reinterpret_cast<uint32_t*>(&Al_s[arow][kh + q * 4])     =
                    (uint32_t)__bfloat16_as_ushort(l[0]) | ((uint32_t)__bfloat16_as_ushort(l[1]) << 16);
                *reinterpret_cast<uint32_t*>(&Al_s[arow][kh + q * 4 + 2]) =
                    (uint32_t)__bfloat16_as_ushort(l[2]) | ((uint32_t)__bfloat16_as_ushort(l[3]) << 16);
            }
        }
        // ---- stage W transposed: [k][64] global -> [n][k] smem ----
#pragma unroll
        for (int i = 0; i < 2; i++) {
            int fid = tid * 2 + i;           // 0..511
            int k  = fid >> 4;               // 0..31
            int n4 = fid & 15;
            float4 f = *reinterpret_cast<const float4*>(&W[(size_t)(kt + k) * 64 + n4 * 4]);
            float vv[4] = {f.x, f.y, f.z, f.w};
#pragma unroll
            for (int j = 0; j < 4; j++) {
                __nv_bfloat16 h, l;
                split_bf16(vv[j], h, l);
                Bh_s[n4 * 4 + j][k] = h;
                Bl_s[n4 * 4 + j][k] = l;
            }
        }
        __syncthreads();

#pragma unroll
        for (int ks = 0; ks < 2; ks++) {
            const int kb = ks * 16;
            const int kcol = kb + 2 * qt;
            uint32_t ah[2][4], al[2][4];
#pragma unroll
            for (int mt = 0; mt < 2; mt++) {
                int R = wrow * 32 + mt * 16 + rg;
                ah[mt][0] = *reinterpret_cast<const uint32_t*>(&Ah_s[R][kcol]);
                ah[mt][1] = *reinterpret_cast<const uint32_t*>(&Ah_s[R + 8][kcol]);
                ah[mt][2] = *reinterpret_cast<const uint32_t*>(&Ah_s[R][kcol + 8]);
                ah[mt][3] = *reinterpret_cast<const uint32_t*>(&Ah_s[R + 8][kcol + 8]);
                al[mt][0] = *reinterpret_cast<const uint32_t*>(&Al_s[R][kcol]);
                al[mt][1] = *reinterpret_cast<const uint32_t*>(&Al_s[R + 8][kcol]);
                al[mt][2] = *reinterpret_cast<const uint32_t*>(&Al_s[R][kcol + 8]);
                al[mt][3] = *reinterpret_cast<const uint32_t*>(&Al_s[R + 8][kcol + 8]);
            }
            uint32_t bh[4][2], bl[4][2];
#pragma unroll
            for (int nt = 0; nt < 4; nt++) {
                int nn = wcol * 32 + nt * 8 + rg;
                bh[nt][0] = *reinterpret_cast<const uint32_t*>(&Bh_s[nn][kcol]);
                bh[nt][1] = *reinterpret_cast<const uint32_t*>(&Bh_s[nn][kcol + 8]);
                bl[nt][0] = *reinterpret_cast<const uint32_t*>(&Bl_s[nn][kcol]);
                bl[nt][1] = *reinterpret_cast<const uint32_t*>(&Bl_s[nn][kcol + 8]);
            }
#pragma unroll
            for (int mt = 0; mt < 2; mt++)
#pragma unroll
                for (int nt = 0; nt < 4; nt++) {
                    float* c = acc[mt][nt];
                    mma_bf16(c[0], c[1], c[2], c[3],
                             al[mt][0], al[mt][1], al[mt][2], al[mt][3],
                             bh[nt][0], bh[nt][1]);
                    mma_bf16(c[0], c[1], c[2], c[3],
                             ah[mt][0], ah[mt][1], ah[mt][2], ah[mt][3],
                             bl[nt][0], bl[nt][1]);
                    mma_bf16(c[0], c[1], c[2], c[3],
                             ah[mt][0], ah[mt][1], ah[mt][2], ah[mt][3],
                             bh[nt][0], bh[nt][1]);
                }
        }
        __syncthreads();
    }

    // ---- epilogue: store C + fused attention logits ----
#pragma unroll
    for (int mt = 0; mt < 2; mt++)
#pragma unroll
        for (int nt = 0; nt < 4; nt++) {
            float* c = acc[mt][nt];
            int r0 = row0 + wrow * 32 + mt * 16 + rg;
            int r1 = r0 + 8;
            int col = wcol * 32 + nt * 8 + qt * 2;
            if (r0 < M)
                *reinterpret_cast<float2*>(&C[(size_t)r0 * 64 + col]) = make_float2(c[0], c[1]);
            if (r1 < M)
                *reinterpret_cast<float2*>(&C[(size_t)r1 * 64 + col]) = make_float2(c[2], c[3]);
            float s0 = __ldg(&att_s[col]), s1 = __ldg(&att_s[col + 1]);
            float d0 = __ldg(&att_d[col]), d1 = __ldg(&att_d[col + 1]);
            float as_a = c[0] * s0 + c[1] * s1;
            float ad_a = c[0] * d0 + c[1] * d1;
            float as_b = c[2] * s0 + c[3] * s1;
            float ad_b = c[2] * d0 + c[3] * d1;
            as_a += __shfl_xor_sync(0xffffffffu, as_a, 1);
            as_a += __shfl_xor_sync(0xffffffffu, as_a, 2);
            ad_a += __shfl_xor_sync(0xffffffffu, ad_a, 1);
            ad_a += __shfl_xor_sync(0xffffffffu, ad_a, 2);
            as_b += __shfl_xor_sync(0xffffffffu, as_b, 1);
            as_b += __shfl_xor_sync(0xffffffffu, as_b, 2);
            ad_b += __shfl_xor_sync(0xffffffffu, ad_b, 1);
            ad_b += __shfl_xor_sync(0xffffffffu, ad_b, 2);
            int head = wcol * 4 + nt;
            if (qt == 0) {
                if (r0 < M) { asrc[r0 * 8 + head] = as_a; adst[r0 * 8 + head] = ad_a; }
                if (r1 < M) { asrc[r1 * 8 + head] = as_b; adst[r1 * 8 + head] = ad_b; }
            }
        }
}

// =======================  layer-2 GEMM (SIMT, fused logits)  ================
template <int BCOLS, int TN, int KTILE>
__global__ void gemm2_kernel(const float* __restrict__ A, int M, int K,
                             const float* __restrict__ W, float* __restrict__ C,
                             const float* __restrict__ att_s, const float* __restrict__ att_d,
                             float* __restrict__ asrc, float* __restrict__ adst) {
    constexpr int BROWS = 256;
    constexpr int TM = 8;
    constexpr int TX = BCOLS / TN;
    constexpr int NT = TX * (BROWS / TM);
    constexpr int PAD = 4;

    __shared__ float xT[KTILE][BROWS + PAD];
    __shared__ float wS[KTILE][BCOLS];
    __shared__ float sAs[BCOLS], sAd[BCOLS];

    const int tid = threadIdx.x;
    const int tx = tid % TX;
    const int ty = tid / TX;
    const int row0 = blockIdx.x * BROWS;

    if (tid < BCOLS) { sAs[tid] = att_s[tid]; sAd[tid] = att_d[tid]; }

    float acc[TM][TN];
#pragma unroll
    for (int i = 0; i < TM; i++)
#pragma unroll
        for (int j = 0; j < TN; j++) acc[i][j] = 0.0f;

    for (int kt = 0; kt < K; kt += KTILE) {
        constexpr int KV = KTILE / 4;
        constexpr int XV = BROWS * KV;
#pragma unroll
        for (int v = tid; v < XV; v += NT) {
            int r  = v / KV;
            int kv = v % KV;
            int grow = row0 + r;
            float4 f = make_float4(0.f, 0.f, 0.f, 0.f);
            if (grow < M)
                f = *reinterpret_cast<const float4*>(&A[(size_t)grow * K + kt + kv * 4]);
            xT[kv * 4 + 0][r] = f.x;
            xT[kv * 4 + 1][r] = f.y;
            xT[kv * 4 + 2][r] = f.z;
            xT[kv * 4 + 3][r] = f.w;
        }
        constexpr int WV = KTILE * BCOLS / 4;
#pragma unroll
        for (int v = tid; v < WV; v += NT) {
            int k = v / (BCOLS / 4);
            int c = v % (BCOLS / 4);
            *reinterpret_cast<float4*>(&wS[k][c * 4]) =
                *reinterpret_cast<const float4*>(&W[(size_t)(kt + k) * BCOLS + c * 4]);
        }
        __syncthreads();

#pragma unroll
        for (int k = 0; k < KTILE; k++) {
            float a[TM];
            *reinterpret_cast<float4*>(&a[0]) = *reinterpret_cast<float4*>(&xT[k][ty * TM]);
            *reinterpret_cast<float4*>(&a[4]) = *reinterpret_cast<float4*>(&xT[k][ty * TM + 4]);
            float b[TN];
#pragma unroll
            for (int j = 0; j < TN; j++) b[j] = wS[k][tx * TN + j];
#pragma unroll
            for (int i = 0; i < TM; i++)
#pragma unroll
                for (int j = 0; j < TN; j++) acc[i][j] = fmaf(a[i], b[j], acc[i][j]);
        }
        __syncthreads();
    }

#pragma unroll
    for (int i = 0; i < TM; i++) {
        int grow = row0 + ty * TM + i;
        if (grow < M) {
#pragma unroll
            for (int j = 0; j < TN; j++) C[(size_t)grow * BCOLS + tx * TN + j] = acc[i][j];
        }
        float as = 0.f, ad = 0.f;
#pragma unroll
        for (int j = 0; j < TN; j++) {
            as = fmaf(acc[i][j], sAs[tx * TN + j], as);
            ad = fmaf(acc[i][j], sAd[tx * TN + j], ad);
        }
#pragma unroll
        for (int off = 4; off; off >>= 1) {
            as += __shfl_xor_sync(0xffffffffu, as, off);
            ad += __shfl_xor_sync(0xffffffffu, ad, off);
        }
        if (tx == 0 && grow < M) { asrc[grow] = as; adst[grow] = ad; }
    }
}

// =======================  layer-1 aggregation (warp per dst)  ===============
__global__ void agg1_kernel(const float* __restrict__ b1, int node0, int node1) {
    __shared__ float wsm[8][32][8];
    const int wid  = threadIdx.x >> 5;
    const int lane = threadIdx.x & 31;
    int node = node0 + ((blockIdx.x * blockDim.x + threadIdx.x) >> 5);
    if (node >= node1) return;

    const int myh = lane & 7;
    const int grp = lane >> 3;
    const int h0  = lane >> 3;
    const int h1f = 4 + h0;

    float adst_l = g_adst1[node * 8 + myh];
    float acc0 = 0.f, acc1 = 0.f, wsum = 0.f;

    int beg = g_rowstart[node], end = g_rowstart[node + 1];
    for (int base = beg; base < end; base += 32) {
        int cnt = min(32, end - base);
        int li = base + lane; if (li >= end) li = end - 1;
        int sl = g_srcs[li];

#pragma unroll
        for (int c = 0; c < 8; c++) {
            int eslot = c * 4 + grp;
            int esrc = __shfl_sync(0xffffffffu, sl, eslot);
            if (eslot < cnt) {
                float a = g_asrc1[esrc * 8 + myh] + adst_l;
                a = a > 0.f ? a : 0.2f * a;
                float w = __expf(a);
                wsum += w;
                wsm[wid][eslot][myh] = w;
            }
        }
        __syncwarp();

#pragma unroll 4
        for (int d = 0; d < cnt; d++) {
            int src = __shfl_sync(0xffffffffu, sl, d);
            float w0 = wsm[wid][d][h0];
            float w1 = wsm[wid][d][h1f];
            const float* hp = &g_h1[(size_t)src * 64];
            acc0 = fmaf(w0, hp[lane],      acc0);
            acc1 = fmaf(w1, hp[32 + lane], acc1);
        }
        __syncwarp();
    }
    wsum += __shfl_xor_sync(0xffffffffu, wsum, 8);
    wsum += __shfl_xor_sync(0xffffffffu, wsum, 16);
    {
        float a = g_asrc1[node * 8 + myh] + adst_l;
        a = a > 0.f ? a : 0.2f * a;
        float wself = __expf(a);
        wsum += wself;
        float w0 = __shfl_sync(0xffffffffu, wself, h0);
        float w1 = __shfl_sync(0xffffffffu, wself, h1f);
        const float* hp = &g_h1[(size_t)node * 64];
        acc0 = fmaf(w0, hp[lane],      acc0);
        acc1 = fmaf(w1, hp[32 + lane], acc1);
    }
    float s0 = __shfl_sync(0xffffffffu, wsum, h0);
    float s1 = __shfl_sync(0xffffffffu, wsum, h1f);
    float t0 = acc0 / (s0 + 1e-16f) + b1[lane];
    float t1 = acc1 / (s1 + 1e-16f) + b1[32 + lane];
    t0 = t0 > 0.f ? t0 : expm1f(t0);
    t1 = t1 > 0.f ? t1 : expm1f(t1);
    g_hf1[(size_t)node * 64 + lane]      = t0;
    g_hf1[(size_t)node * 64 + 32 + lane] = t1;
}

// =======================  layer-2 aggregation + log_softmax  ================
__global__ void agg2_kernel(const float* __restrict__ b2, float* __restrict__ out, int n) {
    int node = (blockIdx.x * blockDim.x + threadIdx.x) >> 5;
    int lane = threadIdx.x & 31;
    if (node >= n) return;

    float adst = g_adst2[node];
    float acc0 = 0.f, acc1 = 0.f, ssum = 0.f;

    int beg = g_rowstart[node], end = g_rowstart[node + 1];
    for (int base = beg; base < end; base += 32) {
        int cnt = min(32, end - base);
        int sl = 0;
        float wl = 0.f;
        if (base + lane < end) {
            sl = g_srcs[base + lane];
            float a = g_asrc2[sl] + adst;
            a = a > 0.f ? a : 0.2f * a;
            wl = __expf(a);
            ssum += wl;
        }
#pragma unroll 4
        for (int d = 0; d < cnt; d++) {
            int src = __shfl_sync(0xffffffffu, sl, d);
            float w  = __shfl_sync(0xffffffffu, wl, d);
            acc0 = fmaf(w, g_h2[(size_t)src * 40 + lane], acc0);
            if (lane < 8)
                acc1 = fmaf(w, g_h2[(size_t)src * 40 + 32 + lane], acc1);
        }
    }
#pragma unroll
    for (int o = 16; o; o >>= 1) ssum += __shfl_xor_sync(0xffffffffu, ssum, o);
    {
        float a = g_asrc2[node] + adst;
        a = a > 0.f ? a : 0.2f * a;
        float w = __expf(a);
        ssum += w;
        acc0 = fmaf(w, g_h2[(size_t)node * 40 + lane], acc0);
        if (lane < 8)
            acc1 = fmaf(w, g_h2[(size_t)node * 40 + 32 + lane], acc1);
    }
    float inv = 1.f / (ssum + 1e-16f);
    float v0 = acc0 * inv + b2[lane];
    float v1 = (lane < 8) ? acc1 * inv + b2[32 + lane] : -3.4e38f;

    float m = fmaxf(v0, v1);
#pragma unroll
    for (int o = 16; o; o >>= 1) m = fmaxf(m, __shfl_xor_sync(0xffffffffu, m, o));
    float es = expf(v0 - m) + (lane < 8 ? expf(v1 - m) : 0.f);
#pragma unroll
    for (int o = 16; o; o >>= 1) es += __shfl_xor_sync(0xffffffffu, es, o);
    float lse = m + logf(es);

    float* dr = &out[(size_t)node * 40];
    dr[lane] = v0 - lse;
    if (lane < 8) dr[32 + lane] = v1 - lse;
}

// ---------------- launch -----------------------------------------------------
static inline int cdiv(int a, int b) { return (a + b - 1) / b; }

extern "C" void kernel_launch(void* const* d_in, const int* in_sizes, int n_in,
                              void* d_out, int out_size) {
    const float* x   = (const float*)d_in[0];
    const int*   ei  = (const int*)d_in[1];
    const float* W1  = (const float*)d_in[2];
    const float* as1 = (const float*)d_in[3];
    const float* ad1 = (const float*)d_in[4];
    const float* b1  = (const float*)d_in[5];
    const float* W2  = (const float*)d_in[6];
    const float* as2 = (const float*)d_in[7];
    const float* ad2 = (const float*)d_in[8];
    const float* b2  = (const float*)d_in[9];
    float*       out = (float*)d_out;

    const int n = in_sizes[0] / 512;      // 100000
    const int E = in_sizes[1] / 2;        // 1600000

    float *p_h1, *p_hf1, *p_h2, *p_as1, *p_ad1, *p_as2, *p_ad2;
    void* p_counts;
    cudaGetSymbolAddress((void**)&p_h1,  g_h1);
    cudaGetSymbolAddress((void**)&p_hf1, g_hf1);
    cudaGetSymbolAddress((void**)&p_h2,  g_h2);
    cudaGetSymbolAddress((void**)&p_as1, g_asrc1);
    cudaGetSymbolAddress((void**)&p_ad1, g_adst1);
    cudaGetSymbolAddress((void**)&p_as2, g_asrc2);
    cudaGetSymbolAddress((void**)&p_ad2, g_adst2);
    cudaGetSymbolAddress(&p_counts, g_counts);

    static cudaStream_t s1 = nullptr;
    static cudaEvent_t ev_fork = nullptr, ev_g1 = nullptr, ev_csr = nullptr, ev_b = nullptr;
    if (s1 == nullptr) {
        cudaStreamCreateWithFlags(&s1, cudaStreamNonBlocking);
        cudaEventCreateWithFlags(&ev_fork, cudaEventDisableTiming);
        cudaEventCreateWithFlags(&ev_g1,   cudaEventDisableTiming);
        cudaEventCreateWithFlags(&ev_csr,  cudaEventDisableTiming);
        cudaEventCreateWithFlags(&ev_b,    cudaEventDisableTiming);
    }

    const int nb_scan = cdiv(n, 1024);
    const int nA = ((n / 2) + 255) & ~255;
    const int nB = n - nA;

    // ---- fork: CSR build on s1 overlapping gemm1 on main -------------------
    cudaEventRecord(ev_fork, 0);
    cudaStreamWaitEvent(s1, ev_fork, 0);

    cudaMemsetAsync(p_counts, 0, n * sizeof(int), s1);
    hist_kernel <<<cdiv(E, 256), 256, 0, s1>>>(ei, E);
    scan_part1  <<<nb_scan, 1024, 0, s1>>>(n);
    scan_part23 <<<nb_scan, 1024, 0, s1>>>(nb_scan, n, E);

    gemm1_bf16<<<cdiv(n, 128), 256>>>(x, n, W1, p_h1,               // kernel 4 (profiled)
                                      as1, ad1, p_as1, p_ad1);
    cudaEventRecord(ev_g1, 0);

    scatter_kernel<<<cdiv(E, 256), 256, 0, s1>>>(ei, E);
    cudaEventRecord(ev_csr, s1);

    // ---- B half on s1 overlapping A half on main ---------------------------
    cudaStreamWaitEvent(s1, ev_g1, 0);
    agg1_kernel<<<cdiv(nB * 32, 256), 256, 0, s1>>>(b1, nA, n);
    gemm2_kernel<40, 5, 32><<<cdiv(nB, 256), 256, 0, s1>>>(
        p_hf1 + (size_t)nA * 64, nB, 64, W2, p_h2 + (size_t)nA * 40,
        as2, ad2, p_as2 + nA, p_ad2 + nA);
    cudaEventRecord(ev_b, s1);

    cudaStreamWaitEvent(0, ev_csr, 0);
    agg1_kernel<<<cdiv(nA * 32, 256), 256>>>(b1, 0, nA);
    gemm2_kernel<40, 5, 32><<<cdiv(nA, 256), 256>>>(
        p_hf1, nA, 64, W2, p_h2, as2, ad2, p_as2, p_ad2);

    cudaStreamWaitEvent(0, ev_b, 0);
    agg2_kernel<<<cdiv(n * 32, 256), 256>>>(b2, out, n);
}

// round 11
// speedup vs baseline: 2.1791x; 1.1014x over previous
#include <cuda_runtime.h>
#include <cuda_bf16.h>
#include <math.h>
#include <stdint.h>

#define NMAX 100000
#define EMAX 1600000

// ---------------- scratch (static __device__, per harness rules) -------------
__device__ float g_h1[NMAX * 64];
__device__ float g_asrc1[NMAX * 8];
__device__ float g_adst1[NMAX * 8];
__device__ float g_hf1[NMAX * 64];
__device__ float g_h2[NMAX * 40];
__device__ float g_asrc2[NMAX];
__device__ float g_adst2[NMAX];

__device__ __nv_bfloat16 g_w1h[64 * 512];   // W1 transposed [n][k], bf16 hi
__device__ __nv_bfloat16 g_w1l[64 * 512];   // W1 transposed [n][k], bf16 lo

__device__ int g_counts[NMAX];
__device__ int g_cursor[NMAX];
__device__ int g_bsum[256];
__device__ int g_rowstart[NMAX + 1];
__device__ int g_srcs[EMAX];

// =======================  helpers  ==========================================

__device__ __forceinline__ uint32_t smem_u32(const void* p) {
    uint32_t a;
    asm("{ .reg .u64 t; cvta.to.shared.u64 t, %1; cvt.u32.u64 %0, t; }" : "=r"(a) : "l"(p));
    return a;
}

#define CP_ASYNC16(dst, src) \
    asm volatile("cp.async.cg.shared.global [%0], [%1], 16;" :: "r"(dst), "l"(src) : "memory")
#define CP_COMMIT() asm volatile("cp.async.commit_group;" ::: "memory")
#define CP_WAIT0()  asm volatile("cp.async.wait_group 0;" ::: "memory")

#define LDSM4(r, a) \
    asm volatile("ldmatrix.sync.aligned.m8n8.x4.shared.b16 {%0,%1,%2,%3}, [%4];" \
                 : "=r"((r)[0]), "=r"((r)[1]), "=r"((r)[2]), "=r"((r)[3]) : "r"(a))
#define LDSM2(r, a) \
    asm volatile("ldmatrix.sync.aligned.m8n8.x2.shared.b16 {%0,%1}, [%2];" \
                 : "=r"((r)[0]), "=r"((r)[1]) : "r"(a))

__device__ __forceinline__ void mma_bf16(float& c0, float& c1, float& c2, float& c3,
                                         uint32_t a0, uint32_t a1, uint32_t a2, uint32_t a3,
                                         uint32_t b0, uint32_t b1) {
    asm volatile("mma.sync.aligned.m16n8k16.row.col.f32.bf16.bf16.f32 "
                 "{%0,%1,%2,%3}, {%4,%5,%6,%7}, {%8,%9}, {%0,%1,%2,%3};"
                 : "+f"(c0), "+f"(c1), "+f"(c2), "+f"(c3)
                 : "r"(a0), "r"(a1), "r"(a2), "r"(a3), "r"(b0), "r"(b1));
}

__device__ __forceinline__ void split_bf16(float v, __nv_bfloat16& hi, __nv_bfloat16& lo) {
    hi = __float2bfloat16(v);
    lo = __float2bfloat16(v - __bfloat162float(hi));
}
__device__ __forceinline__ uint32_t pack2(__nv_bfloat16 a, __nv_bfloat16 b) {
    return (uint32_t)__bfloat16_as_ushort(a) | ((uint32_t)__bfloat16_as_ushort(b) << 16);
}

// =======================  CSR build  ========================================

__global__ void hist_kernel(const int* __restrict__ ei, int E) {
    int e = blockIdx.x * blockDim.x + threadIdx.x;
    if (e >= E) return;
    atomicAdd(&g_counts[ei[E + e]], 1);
}

__global__ void scan_part1(int n) {
    __shared__ int sh[1024];
    int i = blockIdx.x * 1024 + threadIdx.x;
    sh[threadIdx.x] = (i < n) ? g_counts[i] : 0;
    __syncthreads();
#pragma unroll
    for (int off = 512; off; off >>= 1) {
        if (threadIdx.x < off) sh[threadIdx.x] += sh[threadIdx.x + off];
        __syncthreads();
    }
    if (threadIdx.x == 0) g_bsum[blockIdx.x] = sh[0];
}

__global__ void scan_part23(int nb, int n, int E) {
    __shared__ int sh[1024];
    __shared__ int soff;
    int t = threadIdx.x;
    int b = blockIdx.x;
    if (t < 32) {
        int acc = 0;
        for (int i = t; i < b; i += 32) acc += g_bsum[i];
#pragma unroll
        for (int o = 16; o; o >>= 1) acc += __shfl_xor_sync(0xffffffffu, acc, o);
        if (t == 0) soff = acc;
    }
    int i = b * 1024 + t;
    int v = (i < n) ? g_counts[i] : 0;
    sh[t] = v;
    __syncthreads();
#pragma unroll
    for (int off = 1; off < 1024; off <<= 1) {
        int add = (t >= off) ? sh[t - off] : 0;
        __syncthreads();
        sh[t] += add;
        __syncthreads();
    }
    if (i < n) {
        int ex = sh[t] - v + soff;
        g_rowstart[i] = ex;
        g_cursor[i]   = ex;
    }
    if (b == nb - 1 && t == 0) g_rowstart[n] = E;
}

__global__ void scatter_kernel(const int* __restrict__ ei, int E) {
    int e = blockIdx.x * blockDim.x + threadIdx.x;
    if (e >= E) return;
    int src = ei[e];
    int dst = ei[E + e];
    int pos = atomicAdd(&g_cursor[dst], 1);
    g_srcs[pos] = src;
}

// ===================  W1 prep: transpose + bf16 hi/lo split  =================
__global__ void wprep_kernel(const float* __restrict__ W1) {
    int i = blockIdx.x * 256 + threadIdx.x;   // 32768
    int n = i >> 9, k = i & 511;
    float v = W1[(size_t)k * 64 + n];
    __nv_bfloat16 h, l;
    split_bf16(v, h, l);
    g_w1h[i] = h;
    g_w1l[i] = l;
}

// ============  layer-1 GEMM: bf16 3-pass, double-buffered + ldmatrix  ========
// C[M,64] = A[M,512] @ W1 via (Ah+Al)(Wh+Wl) ~= AhWh + AlWh + AhWl.
// BK=32 fp32 k per tile; smem row stride 40 bf16 = 80 B (5x16B -> aligned,
// and 20r mod 32 distinct over 8 rows -> conflict-free ldmatrix + STS).
__global__ __launch_bounds__(256, 2)
void gemm1_v2(const float* __restrict__ A, int M, float* __restrict__ C,
              const float* __restrict__ att_s, const float* __restrict__ att_d,
              float* __restrict__ asrc, float* __restrict__ adst) {
    extern __shared__ char dsm[];
    constexpr int STR  = 40;                  // bf16 elements per row (80 B)
    constexpr int SZ_A = 128 * STR * 2;       // 10240 B  (one of Ah/Al)
    constexpr int SZ_B = 64 * STR * 2;        // 5120 B
    constexpr int STAGE = 2 * SZ_A + 2 * SZ_B;// 30720 B: [Ah][Al][Bh][Bl]
    constexpr int OFF  = 1024;

    const int tid  = threadIdx.x;
    const int lane = tid & 31;
    const int warp = tid >> 5;
    const int wrow = warp >> 1;               // 0..3  (32 rows each)
    const int wcol = warp & 1;                // 0..1  (32 cols each)
    const int row0 = blockIdx.x * 128;
    const uint32_t smb = smem_u32(dsm);

    // A staging map: 8 consecutive tids cover 8 distinct rows -> conflict-free
    const int arow  = tid & 127;              // 0..127
    const int khalf = (tid >> 7) * 16;        // k-offset (fp32) within BK=32
    const int grow  = row0 + arow;
    const bool av   = (grow < M);
    const float* ap = A + (size_t)grow * 512 + khalf;

    float acc[2][4][4];
#pragma unroll
    for (int mt = 0; mt < 2; mt++)
#pragma unroll
        for (int nt = 0; nt < 4; nt++)
#pragma unroll
            for (int r = 0; r < 4; r++) acc[mt][nt][r] = 0.f;

    float rA[16];
    auto ldgA = [&](int kt) {
        if (av) {
#pragma unroll
            for (int q = 0; q < 4; q++)
                *reinterpret_cast<float4*>(&rA[q * 4]) =
                    *reinterpret_cast<const float4*>(ap + kt * 32 + q * 4);
        } else {
#pragma unroll
            for (int q = 0; q < 16; q++) rA[q] = 0.f;
        }
    };
    auto stsA = [&](int st) {
        uint32_t h[8], l[8];
#pragma unroll
        for (int p = 0; p < 8; p++) {
            __nv_bfloat16 h0, l0, h1, l1;
            split_bf16(rA[2 * p], h0, l0);
            split_bf16(rA[2 * p + 1], h1, l1);
            h[p] = pack2(h0, h1);
            l[p] = pack2(l0, l1);
        }
        char* base = dsm + OFF + st * STAGE;
        uint32_t off = (uint32_t)(arow * STR + khalf) * 2;   // 80*arow + 32*half
        *reinterpret_cast<uint4*>(base + off)             = make_uint4(h[0], h[1], h[2], h[3]);
        *reinterpret_cast<uint4*>(base + off + 16)        = make_uint4(h[4], h[5], h[6], h[7]);
        *reinterpret_cast<uint4*>(base + SZ_A + off)      = make_uint4(l[0], l[1], l[2], l[3]);
        *reinterpret_cast<uint4*>(base + SZ_A + off + 16) = make_uint4(l[4], l[5], l[6], l[7]);
    };
    auto cpB = [&](int kt, int st) {
        int nn = tid >> 2, kseg = tid & 3;
        uint32_t dst = smb + OFF + st * STAGE + 2 * SZ_A + (uint32_t)(nn * STR + kseg * 8) * 2;
        CP_ASYNC16(dst,        g_w1h + nn * 512 + kt * 32 + kseg * 8);
        CP_ASYNC16(dst + SZ_B, g_w1l + nn * 512 + kt * 32 + kseg * 8);
    };
    auto compute = [&](int st) {
        uint32_t sb = smb + OFF + st * STAGE;
#pragma unroll
        for (int ks = 0; ks < 2; ks++) {
            uint32_t a0addr = sb + (uint32_t)((wrow * 32 + (lane & 15)) * STR +
                                              (lane >> 4) * 8 + ks * 16) * 2;
            uint32_t ah[2][4], al[2][4];
#pragma unroll
            for (int mt = 0; mt < 2; mt++) {
                uint32_t ad = a0addr + mt * 16 * STR * 2;
                LDSM4(ah[mt], ad);
                LDSM4(al[mt], ad + SZ_A);
            }
            uint32_t b0addr = sb + 2 * SZ_A +
                              (uint32_t)((wcol * 32 + (lane & 7)) * STR +
                                         ((lane >> 3) & 1) * 8 + ks * 16) * 2;
#pragma unroll
            for (int nt = 0; nt < 4; nt++) {
                uint32_t bd = b0addr + nt * 8 * STR * 2;
                uint32_t bh[2], bl[2];
                LDSM2(bh, bd);
                LDSM2(bl, bd + SZ_B);
#pragma unroll
                for (int mt = 0; mt < 2; mt++) {
                    float* c = acc[mt][nt];
                    mma_bf16(c[0], c[1], c[2], c[3],
                             al[mt][0], al[mt][1], al[mt][2], al[mt][3], bh[0], bh[1]);
                    mma_bf16(c[0], c[1], c[2], c[3],
                             ah[mt][0], ah[mt][1], ah[mt][2], ah[mt][3], bl[0], bl[1]);
                    mma_bf16(c[0], c[1], c[2], c[3],
                             ah[mt][0], ah[mt][1], ah[mt][2], ah[mt][3], bh[0], bh[1]);
                }
            }
        }
    };

    // ---- prologue: stage tile 0 ----
    ldgA(0);
    cpB(0, 0);
    CP_COMMIT();
    stsA(0);
    CP_WAIT0();
    __syncthreads();

    // ---- pipelined mainloop: 16 tiles of BK=32 ----
    for (int kt = 0; kt < 16; kt++) {
        int cur = kt & 1;
        if (kt < 15) {
            ldgA(kt + 1);
            cpB(kt + 1, cur ^ 1);
            CP_COMMIT();
        }
        compute(cur);
        if (kt < 15) {
            stsA(cur ^ 1);
            CP_WAIT0();
        }
        __syncthreads();
    }

    // ---- epilogue: store C + fused attention logits (head = col/8) ----
    const int qt = lane & 3;
    const int rg = lane >> 2;
#pragma unroll
    for (int mt = 0; mt < 2; mt++)
#pragma unroll
        for (int nt = 0; nt < 4; nt++) {
            float* c = acc[mt][nt];
            int r0 = row0 + wrow * 32 + mt * 16 + rg;
            int r1 = r0 + 8;
            int col = wcol * 32 + nt * 8 + qt * 2;
            if (r0 < M)
                *reinterpret_cast<float2*>(&C[(size_t)r0 * 64 + col]) = make_float2(c[0], c[1]);
            if (r1 < M)
                *reinterpret_cast<float2*>(&C[(size_t)r1 * 64 + col]) = make_float2(c[2], c[3]);
            float s0 = __ldg(&att_s[col]), s1 = __ldg(&att_s[col + 1]);
            float d0 = __ldg(&att_d[col]), d1 = __ldg(&att_d[col + 1]);
            float as_a = c[0] * s0 + c[1] * s1;
            float ad_a = c[0] * d0 + c[1] * d1;
            float as_b = c[2] * s0 + c[3] * s1;
            float ad_b = c[2] * d0 + c[3] * d1;
            as_a += __shfl_xor_sync(0xffffffffu, as_a, 1);
            as_a += __shfl_xor_sync(0xffffffffu, as_a, 2);
            ad_a += __shfl_xor_sync(0xffffffffu, ad_a, 1);
            ad_a += __shfl_xor_sync(0xffffffffu, ad_a, 2);
            as_b += __shfl_xor_sync(0xffffffffu, as_b, 1);
            as_b += __shfl_xor_sync(0xffffffffu, as_b, 2);
            ad_b += __shfl_xor_sync(0xffffffffu, ad_b, 1);
            ad_b += __shfl_xor_sync(0xffffffffu, ad_b, 2);
            int head = wcol * 4 + nt;
            if (qt == 0) {
                if (r0 < M) { asrc[r0 * 8 + head] = as_a; adst[r0 * 8 + head] = ad_a; }
                if (r1 < M) { asrc[r1 * 8 + head] = as_b; adst[r1 * 8 + head] = ad_b; }
            }
        }
}

// =======================  layer-2 GEMM (SIMT, fused logits)  ================
template <int BCOLS, int TN, int KTILE>
__global__ void gemm2_kernel(const float* __restrict__ A, int M, int K,
                             const float* __restrict__ W, float* __restrict__ C,
                             const float* __restrict__ att_s, const float* __restrict__ att_d,
                             float* __restrict__ asrc, float* __restrict__ adst) {
    constexpr int BROWS = 256;
    constexpr int TM = 8;
    constexpr int TX = BCOLS / TN;
    constexpr int NT = TX * (BROWS / TM);
    constexpr int PAD = 4;

    __shared__ float xT[KTILE][BROWS + PAD];
    __shared__ float wS[KTILE][BCOLS];
    __shared__ float sAs[BCOLS], sAd[BCOLS];

    const int tid = threadIdx.x;
    const int tx = tid % TX;
    const int ty = tid / TX;
    const int row0 = blockIdx.x * BROWS;

    if (tid < BCOLS) { sAs[tid] = att_s[tid]; sAd[tid] = att_d[tid]; }

    float acc[TM][TN];
#pragma unroll
    for (int i = 0; i < TM; i++)
#pragma unroll
        for (int j = 0; j < TN; j++) acc[i][j] = 0.0f;

    for (int kt = 0; kt < K; kt += KTILE) {
        constexpr int KV = KTILE / 4;
        constexpr int XV = BROWS * KV;
#pragma unroll
        for (int v = tid; v < XV; v += NT) {
            int r  = v / KV;
            int kv = v % KV;
            int grow = row0 + r;
            float4 f = make_float4(0.f, 0.f, 0.f, 0.f);
            if (grow < M)
                f = *reinterpret_cast<const float4*>(&A[(size_t)grow * K + kt + kv * 4]);
            xT[kv * 4 + 0][r] = f.x;
            xT[kv * 4 + 1][r] = f.y;
            xT[kv * 4 + 2][r] = f.z;
            xT[kv * 4 + 3][r] = f.w;
        }
        constexpr int WV = KTILE * BCOLS / 4;
#pragma unroll
        for (int v = tid; v < WV; v += NT) {
            int k = v / (BCOLS / 4);
            int c = v % (BCOLS / 4);
            *reinterpret_cast<float4*>(&wS[k][c * 4]) =
                *reinterpret_cast<const float4*>(&W[(size_t)(kt + k) * BCOLS + c * 4]);
        }
        __syncthreads();

#pragma unroll
        for (int k = 0; k < KTILE; k++) {
            float a[TM];
            *reinterpret_cast<float4*>(&a[0]) = *reinterpret_cast<float4*>(&xT[k][ty * TM]);
            *reinterpret_cast<float4*>(&a[4]) = *reinterpret_cast<float4*>(&xT[k][ty * TM + 4]);
            float b[TN];
#pragma unroll
            for (int j = 0; j < TN; j++) b[j] = wS[k][tx * TN + j];
#pragma unroll
            for (int i = 0; i < TM; i++)
#pragma unroll
                for (int j = 0; j < TN; j++) acc[i][j] = fmaf(a[i], b[j], acc[i][j]);
        }
        __syncthreads();
    }

#pragma unroll
    for (int i = 0; i < TM; i++) {
        int grow = row0 + ty * TM + i;
        if (grow < M) {
#pragma unroll
            for (int j = 0; j < TN; j++) C[(size_t)grow * BCOLS + tx * TN + j] = acc[i][j];
        }
        float as = 0.f, ad = 0.f;
#pragma unroll
        for (int j = 0; j < TN; j++) {
            as = fmaf(acc[i][j], sAs[tx * TN + j], as);
            ad = fmaf(acc[i][j], sAd[tx * TN + j], ad);
        }
#pragma unroll
        for (int off = 4; off; off >>= 1) {
            as += __shfl_xor_sync(0xffffffffu, as, off);
            ad += __shfl_xor_sync(0xffffffffu, ad, off);
        }
        if (tx == 0 && grow < M) { asrc[grow] = as; adst[grow] = ad; }
    }
}

// =======================  layer-1 aggregation (warp per dst)  ===============
__global__ void agg1_kernel(const float* __restrict__ b1, int node0, int node1) {
    __shared__ float wsm[8][32][8];
    const int wid  = threadIdx.x >> 5;
    const int lane = threadIdx.x & 31;
    int node = node0 + ((blockIdx.x * blockDim.x + threadIdx.x) >> 5);
    if (node >= node1) return;

    const int myh = lane & 7;
    const int grp = lane >> 3;
    const int h0  = lane >> 3;
    const int h1f = 4 + h0;

    float adst_l = g_adst1[node * 8 + myh];
    float acc0 = 0.f, acc1 = 0.f, wsum = 0.f;

    int beg = g_rowstart[node], end = g_rowstart[node + 1];
    for (int base = beg; base < end; base += 32) {
        int cnt = min(32, end - base);
        int li = base + lane; if (li >= end) li = end - 1;
        int sl = g_srcs[li];

#pragma unroll
        for (int c = 0; c < 8; c++) {
            int eslot = c * 4 + grp;
            int esrc = __shfl_sync(0xffffffffu, sl, eslot);
            if (eslot < cnt) {
                float a = g_asrc1[esrc * 8 + myh] + adst_l;
                a = a > 0.f ? a : 0.2f * a;
                float w = __expf(a);
                wsum += w;
                wsm[wid][eslot][myh] = w;
            }
        }
        __syncwarp();

#pragma unroll 4
        for (int d = 0; d < cnt; d++) {
            int src = __shfl_sync(0xffffffffu, sl, d);
            float w0 = wsm[wid][d][h0];
            float w1 = wsm[wid][d][h1f];
            const float* hp = &g_h1[(size_t)src * 64];
            acc0 = fmaf(w0, hp[lane],      acc0);
            acc1 = fmaf(w1, hp[32 + lane], acc1);
        }
        __syncwarp();
    }
    wsum += __shfl_xor_sync(0xffffffffu, wsum, 8);
    wsum += __shfl_xor_sync(0xffffffffu, wsum, 16);
    {
        float a = g_asrc1[node * 8 + myh] + adst_l;
        a = a > 0.f ? a : 0.2f * a;
        float wself = __expf(a);
        wsum += wself;
        float w0 = __shfl_sync(0xffffffffu, wself, h0);
        float w1 = __shfl_sync(0xffffffffu, wself, h1f);
        const float* hp = &g_h1[(size_t)node * 64];
        acc0 = fmaf(w0, hp[lane],      acc0);
        acc1 = fmaf(w1, hp[32 + lane], acc1);
    }
    float s0 = __shfl_sync(0xffffffffu, wsum, h0);
    float s1 = __shfl_sync(0xffffffffu, wsum, h1f);
    float t0 = acc0 / (s0 + 1e-16f) + b1[lane];
    float t1 = acc1 / (s1 + 1e-16f) + b1[32 + lane];
    t0 = t0 > 0.f ? t0 : expm1f(t0);
    t1 = t1 > 0.f ? t1 : expm1f(t1);
    g_hf1[(size_t)node * 64 + lane]      = t0;
    g_hf1[(size_t)node * 64 + 32 + lane] = t1;
}

// =======================  layer-2 aggregation + log_softmax  ================
__global__ void agg2_kernel(const float* __restrict__ b2, float* __restrict__ out, int n) {
    int node = (blockIdx.x * blockDim.x + threadIdx.x) >> 5;
    int lane = threadIdx.x & 31;
    if (node >= n) return;

    float adst = g_adst2[node];
    float acc0 = 0.f, acc1 = 0.f, ssum = 0.f;

    int beg = g_rowstart[node], end = g_rowstart[node + 1];
    for (int base = beg; base < end; base += 32) {
        int cnt = min(32, end - base);
        int sl = 0;
        float wl = 0.f;
        if (base + lane < end) {
            sl = g_srcs[base + lane];
            float a = g_asrc2[sl] + adst;
            a = a > 0.f ? a : 0.2f * a;
            wl = __expf(a);
            ssum += wl;
        }
#pragma unroll 4
        for (int d = 0; d < cnt; d++) {
            int src = __shfl_sync(0xffffffffu, sl, d);
            float w  = __shfl_sync(0xffffffffu, wl, d);
            acc0 = fmaf(w, g_h2[(size_t)src * 40 + lane], acc0);
            if (lane < 8)
                acc1 = fmaf(w, g_h2[(size_t)src * 40 + 32 + lane], acc1);
        }
    }
#pragma unroll
    for (int o = 16; o; o >>= 1) ssum += __shfl_xor_sync(0xffffffffu, ssum, o);
    {
        float a = g_asrc2[node] + adst;
        a = a > 0.f ? a : 0.2f * a;
        float w = __expf(a);
        ssum += w;
        acc0 = fmaf(w, g_h2[(size_t)node * 40 + lane], acc0);
        if (lane < 8)
            acc1 = fmaf(w, g_h2[(size_t)node * 40 + 32 + lane], acc1);
    }
    float inv = 1.f / (ssum + 1e-16f);
    float v0 = acc0 * inv + b2[lane];
    float v1 = (lane < 8) ? acc1 * inv + b2[32 + lane] : -3.4e38f;

    float m = fmaxf(v0, v1);
#pragma unroll
    for (int o = 16; o; o >>= 1) m = fmaxf(m, __shfl_xor_sync(0xffffffffu, m, o));
    float es = expf(v0 - m) + (lane < 8 ? expf(v1 - m) : 0.f);
#pragma unroll
    for (int o = 16; o; o >>= 1) es += __shfl_xor_sync(0xffffffffu, es, o);
    float lse = m + logf(es);

    float* dr = &out[(size_t)node * 40];
    dr[lane] = v0 - lse;
    if (lane < 8) dr[32 + lane] = v1 - lse;
}

// ---------------- launch -----------------------------------------------------
static inline int cdiv(int a, int b) { return (a + b - 1) / b; }

extern "C" void kernel_launch(void* const* d_in, const int* in_sizes, int n_in,
                              void* d_out, int out_size) {
    const float* x   = (const float*)d_in[0];
    const int*   ei  = (const int*)d_in[1];
    const float* W1  = (const float*)d_in[2];
    const float* as1 = (const float*)d_in[3];
    const float* ad1 = (const float*)d_in[4];
    const float* b1  = (const float*)d_in[5];
    const float* W2  = (const float*)d_in[6];
    const float* as2 = (const float*)d_in[7];
    const float* ad2 = (const float*)d_in[8];
    const float* b2  = (const float*)d_in[9];
    float*       out = (float*)d_out;

    const int n = in_sizes[0] / 512;      // 100000
    const int E = in_sizes[1] / 2;        // 1600000
    // dyn smem: 1024 + 2 stages * (2*10240 + 2*5120) = 62464
    const int SMEM_G1 = 1024 + 2 * (2 * 10240 + 2 * 5120);

    float *p_h1, *p_hf1, *p_h2, *p_as1, *p_ad1, *p_as2, *p_ad2;
    void* p_counts;
    cudaGetSymbolAddress((void**)&p_h1,  g_h1);
    cudaGetSymbolAddress((void**)&p_hf1, g_hf1);
    cudaGetSymbolAddress((void**)&p_h2,  g_h2);
    cudaGetSymbolAddress((void**)&p_as1, g_asrc1);
    cudaGetSymbolAddress((void**)&p_ad1, g_adst1);
    cudaGetSymbolAddress((void**)&p_as2, g_asrc2);
    cudaGetSymbolAddress((void**)&p_ad2, g_adst2);
    cudaGetSymbolAddress(&p_counts, g_counts);

    static cudaStream_t s1 = nullptr, s2 = nullptr;
    static cudaEvent_t ev_fork = nullptr, ev_w = nullptr, ev_g1 = nullptr,
                       ev_csr = nullptr, ev_b = nullptr;
    if (s1 == nullptr) {
        cudaStreamCreateWithFlags(&s1, cudaStreamNonBlocking);
        cudaStreamCreateWithFlags(&s2, cudaStreamNonBlocking);
        cudaEventCreateWithFlags(&ev_fork, cudaEventDisableTiming);
        cudaEventCreateWithFlags(&ev_w,    cudaEventDisableTiming);
        cudaEventCreateWithFlags(&ev_g1,   cudaEventDisableTiming);
        cudaEventCreateWithFlags(&ev_csr,  cudaEventDisableTiming);
        cudaEventCreateWithFlags(&ev_b,    cudaEventDisableTiming);
        cudaFuncSetAttribute(gemm1_v2, cudaFuncAttributeMaxDynamicSharedMemorySize, SMEM_G1);
    }

    const int nb_scan = cdiv(n, 1024);
    const int nA = ((n / 2) + 255) & ~255;
    const int nB = n - nA;

    // ---- fork -------------------------------------------------------------
    cudaEventRecord(ev_fork, 0);
    cudaStreamWaitEvent(s1, ev_fork, 0);
    cudaStreamWaitEvent(s2, ev_fork, 0);

    cudaMemsetAsync(p_counts, 0, n * sizeof(int), s1);                 // (1)
    hist_kernel <<<cdiv(E, 256), 256, 0, s1>>>(ei, E);                 // (2)
    scan_part1  <<<nb_scan, 1024, 0, s1>>>(n);                         // (3)

    wprep_kernel<<<128, 256, 0, s2>>>(W1);                             // (4)
    cudaEventRecord(ev_w, s2);

    cudaStreamWaitEvent(0, ev_w, 0);
    gemm1_v2<<<cdiv(n, 128), 256, SMEM_G1>>>(x, n, p_h1,               // (5) profiled
                                             as1, ad1, p_as1, p_ad1);
    cudaEventRecord(ev_g1, 0);

    scan_part23 <<<nb_scan, 1024, 0, s1>>>(nb_scan, n, E);             // (6)
    scatter_kernel<<<cdiv(E, 256), 256, 0, s1>>>(ei, E);               // (7)
    cudaEventRecord(ev_csr, s1);

    // ---- B half on s1 overlapping A half on main ---------------------------
    cudaStreamWaitEvent(s1, ev_g1, 0);
    agg1_kernel<<<cdiv(nB * 32, 256), 256, 0, s1>>>(b1, nA, n);
    gemm2_kernel<40, 5, 32><<<cdiv(nB, 256), 256, 0, s1>>>(
        p_hf1 + (size_t)nA * 64, nB, 64, W2, p_h2 + (size_t)nA * 40,
        as2, ad2, p_as2 + nA, p_ad2 + nA);
    cudaEventRecord(ev_b, s1);

    cudaStreamWaitEvent(0, ev_csr, 0);
    agg1_kernel<<<cdiv(nA * 32, 256), 256>>>(b1, 0, nA);
    gemm2_kernel<40, 5, 32><<<cdiv(nA, 256), 256>>>(
        p_hf1, nA, 64, W2, p_h2, as2, ad2, p_as2, p_ad2);

    cudaStreamWaitEvent(0, ev_b, 0);
    agg2_kernel<<<cdiv(n * 32, 256), 256>>>(b2, out, n);
}

// round 12
// speedup vs baseline: 2.2233x; 1.0203x over previous
#include <cuda_runtime.h>
#include <cuda_bf16.h>
#include <math.h>
#include <stdint.h>

#define NMAX 100000
#define EMAX 1600000

// ---------------- scratch (static __device__, per harness rules) -------------
__device__ float g_h1[NMAX * 64];
__device__ float g_asrc1[NMAX * 8];
__device__ float g_adst1[NMAX * 8];
__device__ float g_hf1[NMAX * 64];
__device__ float g_h2[NMAX * 40];
__device__ float g_asrc2[NMAX];
__device__ float g_adst2[NMAX];

__device__ __nv_bfloat16 g_w1h[64 * 512];   // W1 transposed [n][k], bf16 hi
__device__ __nv_bfloat16 g_w1l[64 * 512];   // W1 transposed [n][k], bf16 lo

__device__ int g_counts[NMAX];
__device__ int g_cursor[NMAX];
__device__ int g_bsum[256];
__device__ int g_rowstart[NMAX + 1];
__device__ int g_srcs[EMAX];

// =======================  helpers  ==========================================

__device__ __forceinline__ uint32_t smem_u32(const void* p) {
    uint32_t a;
    asm("{ .reg .u64 t; cvta.to.shared.u64 t, %1; cvt.u32.u64 %0, t; }" : "=r"(a) : "l"(p));
    return a;
}

#define CP_ASYNC16(dst, src) \
    asm volatile("cp.async.cg.shared.global [%0], [%1], 16;" :: "r"(dst), "l"(src) : "memory")
#define CP_COMMIT() asm volatile("cp.async.commit_group;" ::: "memory")
#define CP_WAIT0()  asm volatile("cp.async.wait_group 0;" ::: "memory")

#define LDSM4(r, a) \
    asm volatile("ldmatrix.sync.aligned.m8n8.x4.shared.b16 {%0,%1,%2,%3}, [%4];" \
                 : "=r"((r)[0]), "=r"((r)[1]), "=r"((r)[2]), "=r"((r)[3]) : "r"(a))

__device__ __forceinline__ void mma_bf16(float& c0, float& c1, float& c2, float& c3,
                                         uint32_t a0, uint32_t a1, uint32_t a2, uint32_t a3,
                                         uint32_t b0, uint32_t b1) {
    asm volatile("mma.sync.aligned.m16n8k16.row.col.f32.bf16.bf16.f32 "
                 "{%0,%1,%2,%3}, {%4,%5,%6,%7}, {%8,%9}, {%0,%1,%2,%3};"
                 : "+f"(c0), "+f"(c1), "+f"(c2), "+f"(c3)
                 : "r"(a0), "r"(a1), "r"(a2), "r"(a3), "r"(b0), "r"(b1));
}

__device__ __forceinline__ void split_bf16(float v, __nv_bfloat16& hi, __nv_bfloat16& lo) {
    hi = __float2bfloat16(v);
    lo = __float2bfloat16(v - __bfloat162float(hi));
}
__device__ __forceinline__ uint32_t pack2(__nv_bfloat16 a, __nv_bfloat16 b) {
    return (uint32_t)__bfloat16_as_ushort(a) | ((uint32_t)__bfloat16_as_ushort(b) << 16);
}

// =======================  CSR build  ========================================

__global__ void hist_kernel(const int* __restrict__ ei, int E) {
    int e = blockIdx.x * blockDim.x + threadIdx.x;
    if (e >= E) return;
    atomicAdd(&g_counts[ei[E + e]], 1);
}

__global__ void scan_part1(int n) {
    __shared__ int sh[1024];
    int i = blockIdx.x * 1024 + threadIdx.x;
    sh[threadIdx.x] = (i < n) ? g_counts[i] : 0;
    __syncthreads();
#pragma unroll
    for (int off = 512; off; off >>= 1) {
        if (threadIdx.x < off) sh[threadIdx.x] += sh[threadIdx.x + off];
        __syncthreads();
    }
    if (threadIdx.x == 0) g_bsum[blockIdx.x] = sh[0];
}

__global__ void scan_part23(int nb, int n, int E) {
    __shared__ int sh[1024];
    __shared__ int soff;
    int t = threadIdx.x;
    int b = blockIdx.x;
    if (t < 32) {
        int acc = 0;
        for (int i = t; i < b; i += 32) acc += g_bsum[i];
#pragma unroll
        for (int o = 16; o; o >>= 1) acc += __shfl_xor_sync(0xffffffffu, acc, o);
        if (t == 0) soff = acc;
    }
    int i = b * 1024 + t;
    int v = (i < n) ? g_counts[i] : 0;
    sh[t] = v;
    __syncthreads();
#pragma unroll
    for (int off = 1; off < 1024; off <<= 1) {
        int add = (t >= off) ? sh[t - off] : 0;
        __syncthreads();
        sh[t] += add;
        __syncthreads();
    }
    if (i < n) {
        int ex = sh[t] - v + soff;
        g_rowstart[i] = ex;
        g_cursor[i]   = ex;
    }
    if (b == nb - 1 && t == 0) g_rowstart[n] = E;
}

__global__ void scatter_kernel(const int* __restrict__ ei, int E) {
    int e = blockIdx.x * blockDim.x + threadIdx.x;
    if (e >= E) return;
    int src = ei[e];
    int dst = ei[E + e];
    int pos = atomicAdd(&g_cursor[dst], 1);
    g_srcs[pos] = src;
}

// ===================  W1 prep: transpose + bf16 hi/lo split  =================
__global__ void wprep_kernel(const float* __restrict__ W1) {
    int i = blockIdx.x * 256 + threadIdx.x;   // 32768
    int n = i >> 9, k = i & 511;
    float v = W1[(size_t)k * 64 + n];
    __nv_bfloat16 h, l;
    split_bf16(v, h, l);
    g_w1h[i] = h;
    g_w1l[i] = l;
}

// ============  layer-1 GEMM: bf16 3-pass, double-buffered + ldmatrix  ========
// STR=40 bf16 = 80B rows: 16B-aligned, 20r mod 32 distinct over 8 rows.
// B fragments: ldmatrix.x4 covers 2 nt at once.
__global__ __launch_bounds__(256, 3)
void gemm1_v2(const float* __restrict__ A, int M, float* __restrict__ C,
              const float* __restrict__ att_s, const float* __restrict__ att_d,
              float* __restrict__ asrc, float* __restrict__ adst) {
    extern __shared__ char dsm[];
    constexpr int STR  = 40;
    constexpr int SZ_A = 128 * STR * 2;       // 10240 B
    constexpr int SZ_B = 64 * STR * 2;        // 5120 B
    constexpr int STAGE = 2 * SZ_A + 2 * SZ_B;// 30720 B
    constexpr int OFF  = 1024;

    const int tid  = threadIdx.x;
    const int lane = tid & 31;
    const int warp = tid >> 5;
    const int wrow = warp >> 1;
    const int wcol = warp & 1;
    const int row0 = blockIdx.x * 128;
    const uint32_t smb = smem_u32(dsm);

    const int arow  = tid & 127;
    const int khalf = (tid >> 7) * 16;
    const int grow  = row0 + arow;
    const bool av   = (grow < M);
    const float* ap = A + (size_t)grow * 512 + khalf;

    float acc[2][4][4];
#pragma unroll
    for (int mt = 0; mt < 2; mt++)
#pragma unroll
        for (int nt = 0; nt < 4; nt++)
#pragma unroll
            for (int r = 0; r < 4; r++) acc[mt][nt][r] = 0.f;

    float rA[16];
    auto ldgA = [&](int kt) {
        if (av) {
#pragma unroll
            for (int q = 0; q < 4; q++)
                *reinterpret_cast<float4*>(&rA[q * 4]) =
                    *reinterpret_cast<const float4*>(ap + kt * 32 + q * 4);
        } else {
#pragma unroll
            for (int q = 0; q < 16; q++) rA[q] = 0.f;
        }
    };
    auto stsA = [&](int st) {
        uint32_t h[8], l[8];
#pragma unroll
        for (int p = 0; p < 8; p++) {
            __nv_bfloat16 h0, l0, h1, l1;
            split_bf16(rA[2 * p], h0, l0);
            split_bf16(rA[2 * p + 1], h1, l1);
            h[p] = pack2(h0, h1);
            l[p] = pack2(l0, l1);
        }
        char* base = dsm + OFF + st * STAGE;
        uint32_t off = (uint32_t)(arow * STR + khalf) * 2;
        *reinterpret_cast<uint4*>(base + off)             = make_uint4(h[0], h[1], h[2], h[3]);
        *reinterpret_cast<uint4*>(base + off + 16)        = make_uint4(h[4], h[5], h[6], h[7]);
        *reinterpret_cast<uint4*>(base + SZ_A + off)      = make_uint4(l[0], l[1], l[2], l[3]);
        *reinterpret_cast<uint4*>(base + SZ_A + off + 16) = make_uint4(l[4], l[5], l[6], l[7]);
    };
    auto cpB = [&](int kt, int st) {
        int nn = tid >> 2, kseg = tid & 3;
        uint32_t dst = smb + OFF + st * STAGE + 2 * SZ_A + (uint32_t)(nn * STR + kseg * 8) * 2;
        CP_ASYNC16(dst,        g_w1h + nn * 512 + kt * 32 + kseg * 8);
        CP_ASYNC16(dst + SZ_B, g_w1l + nn * 512 + kt * 32 + kseg * 8);
    };
    auto compute = [&](int st) {
        uint32_t sb = smb + OFF + st * STAGE;
#pragma unroll
        for (int ks = 0; ks < 2; ks++) {
            uint32_t a0addr = sb + (uint32_t)((wrow * 32 + (lane & 15)) * STR +
                                              (lane >> 4) * 8 + ks * 16) * 2;
            uint32_t ah[2][4], al[2][4];
#pragma unroll
            for (int mt = 0; mt < 2; mt++) {
                uint32_t ad = a0addr + mt * 16 * STR * 2;
                LDSM4(ah[mt], ad);
                LDSM4(al[mt], ad + SZ_A);
            }
            // B: x4 covers 2 nt (16 n-rows) x 2 k-halves per load
#pragma unroll
            for (int np = 0; np < 2; np++) {
                uint32_t bd = sb + 2 * SZ_A +
                              (uint32_t)((wcol * 32 + np * 16 + ((lane >> 4) << 3) + (lane & 7)) * STR +
                                         ks * 16 + (((lane >> 3) & 1) << 3)) * 2;
                uint32_t bh4[4], bl4[4];
                LDSM4(bh4, bd);
                LDSM4(bl4, bd + SZ_B);
#pragma unroll
                for (int n2 = 0; n2 < 2; n2++) {
                    int nt = np * 2 + n2;
                    uint32_t b0h = bh4[n2 * 2], b1h = bh4[n2 * 2 + 1];
                    uint32_t b0l = bl4[n2 * 2], b1l = bl4[n2 * 2 + 1];
#pragma unroll
                    for (int mt = 0; mt < 2; mt++) {
                        float* c = acc[mt][nt];
                        mma_bf16(c[0], c[1], c[2], c[3],
                                 al[mt][0], al[mt][1], al[mt][2], al[mt][3], b0h, b1h);
                        mma_bf16(c[0], c[1], c[2], c[3],
                                 ah[mt][0], ah[mt][1], ah[mt][2], ah[mt][3], b0l, b1l);
                        mma_bf16(c[0], c[1], c[2], c[3],
                                 ah[mt][0], ah[mt][1], ah[mt][2], ah[mt][3], b0h, b1h);
                    }
                }
            }
        }
    };

    // ---- prologue ----
    ldgA(0);
    cpB(0, 0);
    CP_COMMIT();
    stsA(0);
    CP_WAIT0();
    __syncthreads();

    // ---- pipelined mainloop: 16 tiles of BK=32 ----
    for (int kt = 0; kt < 16; kt++) {
        int cur = kt & 1;
        if (kt < 15) {
            ldgA(kt + 1);
            cpB(kt + 1, cur ^ 1);
            CP_COMMIT();
        }
        compute(cur);
        if (kt < 15) {
            stsA(cur ^ 1);
            CP_WAIT0();
        }
        __syncthreads();
    }

    // ---- epilogue: store C + fused attention logits ----
    const int qt = lane & 3;
    const int rg = lane >> 2;
#pragma unroll
    for (int mt = 0; mt < 2; mt++)
#pragma unroll
        for (int nt = 0; nt < 4; nt++) {
            float* c = acc[mt][nt];
            int r0 = row0 + wrow * 32 + mt * 16 + rg;
            int r1 = r0 + 8;
            int col = wcol * 32 + nt * 8 + qt * 2;
            if (r0 < M)
                *reinterpret_cast<float2*>(&C[(size_t)r0 * 64 + col]) = make_float2(c[0], c[1]);
            if (r1 < M)
                *reinterpret_cast<float2*>(&C[(size_t)r1 * 64 + col]) = make_float2(c[2], c[3]);
            float s0 = __ldg(&att_s[col]), s1 = __ldg(&att_s[col + 1]);
            float d0 = __ldg(&att_d[col]), d1 = __ldg(&att_d[col + 1]);
            float as_a = c[0] * s0 + c[1] * s1;
            float ad_a = c[0] * d0 + c[1] * d1;
            float as_b = c[2] * s0 + c[3] * s1;
            float ad_b = c[2] * d0 + c[3] * d1;
            as_a += __shfl_xor_sync(0xffffffffu, as_a, 1);
            as_a += __shfl_xor_sync(0xffffffffu, as_a, 2);
            ad_a += __shfl_xor_sync(0xffffffffu, ad_a, 1);
            ad_a += __shfl_xor_sync(0xffffffffu, ad_a, 2);
            as_b += __shfl_xor_sync(0xffffffffu, as_b, 1);
            as_b += __shfl_xor_sync(0xffffffffu, as_b, 2);
            ad_b += __shfl_xor_sync(0xffffffffu, ad_b, 1);
            ad_b += __shfl_xor_sync(0xffffffffu, ad_b, 2);
            int head = wcol * 4 + nt;
            if (qt == 0) {
                if (r0 < M) { asrc[r0 * 8 + head] = as_a; adst[r0 * 8 + head] = ad_a; }
                if (r1 < M) { asrc[r1 * 8 + head] = as_b; adst[r1 * 8 + head] = ad_b; }
            }
        }
}

// =======================  layer-2 GEMM (SIMT, fused logits)  ================
template <int BCOLS, int TN, int KTILE>
__global__ void gemm2_kernel(const float* __restrict__ A, int M, int K,
                             const float* __restrict__ W, float* __restrict__ C,
                             const float* __restrict__ att_s, const float* __restrict__ att_d,
                             float* __restrict__ asrc, float* __restrict__ adst) {
    constexpr int BROWS = 256;
    constexpr int TM = 8;
    constexpr int TX = BCOLS / TN;
    constexpr int NT = TX * (BROWS / TM);
    constexpr int PAD = 4;

    __shared__ float xT[KTILE][BROWS + PAD];
    __shared__ float wS[KTILE][BCOLS];
    __shared__ float sAs[BCOLS], sAd[BCOLS];

    const int tid = threadIdx.x;
    const int tx = tid % TX;
    const int ty = tid / TX;
    const int row0 = blockIdx.x * BROWS;

    if (tid < BCOLS) { sAs[tid] = att_s[tid]; sAd[tid] = att_d[tid]; }

    float acc[TM][TN];
#pragma unroll
    for (int i = 0; i < TM; i++)
#pragma unroll
        for (int j = 0; j < TN; j++) acc[i][j] = 0.0f;

    for (int kt = 0; kt < K; kt += KTILE) {
        constexpr int KV = KTILE / 4;
        constexpr int XV = BROWS * KV;
#pragma unroll
        for (int v = tid; v < XV; v += NT) {
            int r  = v / KV;
            int kv = v % KV;
            int grow = row0 + r;
            float4 f = make_float4(0.f, 0.f, 0.f, 0.f);
            if (grow < M)
                f = *reinterpret_cast<const float4*>(&A[(size_t)grow * K + kt + kv * 4]);
            xT[kv * 4 + 0][r] = f.x;
            xT[kv * 4 + 1][r] = f.y;
            xT[kv * 4 + 2][r] = f.z;
            xT[kv * 4 + 3][r] = f.w;
        }
        constexpr int WV = KTILE * BCOLS / 4;
#pragma unroll
        for (int v = tid; v < WV; v += NT) {
            int k = v / (BCOLS / 4);
            int c = v % (BCOLS / 4);
            *reinterpret_cast<float4*>(&wS[k][c * 4]) =
                *reinterpret_cast<const float4*>(&W[(size_t)(kt + k) * BCOLS + c * 4]);
        }
        __syncthreads();

#pragma unroll
        for (int k = 0; k < KTILE; k++) {
            float a[TM];
            *reinterpret_cast<float4*>(&a[0]) = *reinterpret_cast<float4*>(&xT[k][ty * TM]);
            *reinterpret_cast<float4*>(&a[4]) = *reinterpret_cast<float4*>(&xT[k][ty * TM + 4]);
            float b[TN];
#pragma unroll
            for (int j = 0; j < TN; j++) b[j] = wS[k][tx * TN + j];
#pragma unroll
            for (int i = 0; i < TM; i++)
#pragma unroll
                for (int j = 0; j < TN; j++) acc[i][j] = fmaf(a[i], b[j], acc[i][j]);
        }
        __syncthreads();
    }

#pragma unroll
    for (int i = 0; i < TM; i++) {
        int grow = row0 + ty * TM + i;
        if (grow < M) {
#pragma unroll
            for (int j = 0; j < TN; j++) C[(size_t)grow * BCOLS + tx * TN + j] = acc[i][j];
        }
        float as = 0.f, ad = 0.f;
#pragma unroll
        for (int j = 0; j < TN; j++) {
            as = fmaf(acc[i][j], sAs[tx * TN + j], as);
            ad = fmaf(acc[i][j], sAd[tx * TN + j], ad);
        }
#pragma unroll
        for (int off = 4; off; off >>= 1) {
            as += __shfl_xor_sync(0xffffffffu, as, off);
            ad += __shfl_xor_sync(0xffffffffu, ad, off);
        }
        if (tx == 0 && grow < M) { asrc[grow] = as; adst[grow] = ad; }
    }
}

// =======================  layer-1 aggregation (warp per dst)  ===============
__global__ void agg1_kernel(const float* __restrict__ b1, int node0, int node1) {
    __shared__ float wsm[8][32][8];
    const int wid  = threadIdx.x >> 5;
    const int lane = threadIdx.x & 31;
    int node = node0 + ((blockIdx.x * blockDim.x + threadIdx.x) >> 5);
    if (node >= node1) return;

    const int myh = lane & 7;
    const int grp = lane >> 3;
    const int h0  = lane >> 3;
    const int h1f = 4 + h0;

    float adst_l = g_adst1[node * 8 + myh];
    float acc0 = 0.f, acc1 = 0.f, wsum = 0.f;

    int beg = g_rowstart[node], end = g_rowstart[node + 1];
    for (int base = beg; base < end; base += 32) {
        int cnt = min(32, end - base);
        int li = base + lane; if (li >= end) li = end - 1;
        int sl = g_srcs[li];

#pragma unroll
        for (int c = 0; c < 8; c++) {
            int eslot = c * 4 + grp;
            int esrc = __shfl_sync(0xffffffffu, sl, eslot);
            if (eslot < cnt) {
                float a = g_asrc1[esrc * 8 + myh] + adst_l;
                a = a > 0.f ? a : 0.2f * a;
                float w = __expf(a);
                wsum += w;
                wsm[wid][eslot][myh] = w;
            }
        }
        __syncwarp();

#pragma unroll 8
        for (int d = 0; d < cnt; d++) {
            int src = __shfl_sync(0xffffffffu, sl, d);
            float w0 = wsm[wid][d][h0];
            float w1 = wsm[wid][d][h1f];
            const float* hp = &g_h1[(size_t)src * 64];
            acc0 = fmaf(w0, hp[lane],      acc0);
            acc1 = fmaf(w1, hp[32 + lane], acc1);
        }
        __syncwarp();
    }
    wsum += __shfl_xor_sync(0xffffffffu, wsum, 8);
    wsum += __shfl_xor_sync(0xffffffffu, wsum, 16);
    {
        float a = g_asrc1[node * 8 + myh] + adst_l;
        a = a > 0.f ? a : 0.2f * a;
        float wself = __expf(a);
        wsum += wself;
        float w0 = __shfl_sync(0xffffffffu, wself, h0);
        float w1 = __shfl_sync(0xffffffffu, wself, h1f);
        const float* hp = &g_h1[(size_t)node * 64];
        acc0 = fmaf(w0, hp[lane],      acc0);
        acc1 = fmaf(w1, hp[32 + lane], acc1);
    }
    float s0 = __shfl_sync(0xffffffffu, wsum, h0);
    float s1 = __shfl_sync(0xffffffffu, wsum, h1f);
    float t0 = acc0 / (s0 + 1e-16f) + b1[lane];
    float t1 = acc1 / (s1 + 1e-16f) + b1[32 + lane];
    t0 = t0 > 0.f ? t0 : expm1f(t0);
    t1 = t1 > 0.f ? t1 : expm1f(t1);
    g_hf1[(size_t)node * 64 + lane]      = t0;
    g_hf1[(size_t)node * 64 + 32 + lane] = t1;
}

// =======================  layer-2 aggregation + log_softmax  ================
__global__ void agg2_kernel(const float* __restrict__ b2, float* __restrict__ out, int n) {
    int node = (blockIdx.x * blockDim.x + threadIdx.x) >> 5;
    int lane = threadIdx.x & 31;
    if (node >= n) return;

    float adst = g_adst2[node];
    float acc0 = 0.f, acc1 = 0.f, ssum = 0.f;

    int beg = g_rowstart[node], end = g_rowstart[node + 1];
    for (int base = beg; base < end; base += 32) {
        int cnt = min(32, end - base);
        int sl = 0;
        float wl = 0.f;
        if (base + lane < end) {
            sl = g_srcs[base + lane];
            float a = g_asrc2[sl] + adst;
            a = a > 0.f ? a : 0.2f * a;
            wl = __expf(a);
            ssum += wl;
        }
#pragma unroll 8
        for (int d = 0; d < cnt; d++) {
            int src = __shfl_sync(0xffffffffu, sl, d);
            float w  = __shfl_sync(0xffffffffu, wl, d);
            acc0 = fmaf(w, g_h2[(size_t)src * 40 + lane], acc0);
            if (lane < 8)
                acc1 = fmaf(w, g_h2[(size_t)src * 40 + 32 + lane], acc1);
        }
    }
#pragma unroll
    for (int o = 16; o; o >>= 1) ssum += __shfl_xor_sync(0xffffffffu, ssum, o);
    {
        float a = g_asrc2[node] + adst;
        a = a > 0.f ? a : 0.2f * a;
        float w = __expf(a);
        ssum += w;
        acc0 = fmaf(w, g_h2[(size_t)node * 40 + lane], acc0);
        if (lane < 8)
            acc1 = fmaf(w, g_h2[(size_t)node * 40 + 32 + lane], acc1);
    }
    float inv = 1.f / (ssum + 1e-16f);
    float v0 = acc0 * inv + b2[lane];
    float v1 = (lane < 8) ? acc1 * inv + b2[32 + lane] : -3.4e38f;

    float m = fmaxf(v0, v1);
#pragma unroll
    for (int o = 16; o; o >>= 1) m = fmaxf(m, __shfl_xor_sync(0xffffffffu, m, o));
    float es = expf(v0 - m) + (lane < 8 ? expf(v1 - m) : 0.f);
#pragma unroll
    for (int o = 16; o; o >>= 1) es += __shfl_xor_sync(0xffffffffu, es, o);
    float lse = m + logf(es);

    float* dr = &out[(size_t)node * 40];
    dr[lane] = v0 - lse;
    if (lane < 8) dr[32 + lane] = v1 - lse;
}

// ---------------- launch -----------------------------------------------------
static inline int cdiv(int a, int b) { return (a + b - 1) / b; }

extern "C" void kernel_launch(void* const* d_in, const int* in_sizes, int n_in,
                              void* d_out, int out_size) {
    const float* x   = (const float*)d_in[0];
    const int*   ei  = (const int*)d_in[1];
    const float* W1  = (const float*)d_in[2];
    const float* as1 = (const float*)d_in[3];
    const float* ad1 = (const float*)d_in[4];
    const float* b1  = (const float*)d_in[5];
    const float* W2  = (const float*)d_in[6];
    const float* as2 = (const float*)d_in[7];
    const float* ad2 = (const float*)d_in[8];
    const float* b2  = (const float*)d_in[9];
    float*       out = (float*)d_out;

    const int n = in_sizes[0] / 512;      // 100000
    const int E = in_sizes[1] / 2;        // 1600000
    const int SMEM_G1 = 1024 + 2 * (2 * 10240 + 2 * 5120);   // 62464

    float *p_h1, *p_hf1, *p_h2, *p_as1, *p_ad1, *p_as2, *p_ad2;
    void* p_counts;
    cudaGetSymbolAddress((void**)&p_h1,  g_h1);
    cudaGetSymbolAddress((void**)&p_hf1, g_hf1);
    cudaGetSymbolAddress((void**)&p_h2,  g_h2);
    cudaGetSymbolAddress((void**)&p_as1, g_asrc1);
    cudaGetSymbolAddress((void**)&p_ad1, g_adst1);
    cudaGetSymbolAddress((void**)&p_as2, g_asrc2);
    cudaGetSymbolAddress((void**)&p_ad2, g_adst2);
    cudaGetSymbolAddress(&p_counts, g_counts);

    static cudaStream_t s1 = nullptr, s2 = nullptr;
    static cudaEvent_t ev_fork = nullptr, ev_w = nullptr, ev_g1 = nullptr,
                       ev_csr = nullptr, ev_b = nullptr;
    if (s1 == nullptr) {
        cudaStreamCreateWithFlags(&s1, cudaStreamNonBlocking);
        cudaStreamCreateWithFlags(&s2, cudaStreamNonBlocking);
        cudaEventCreateWithFlags(&ev_fork, cudaEventDisableTiming);
        cudaEventCreateWithFlags(&ev_w,    cudaEventDisableTiming);
        cudaEventCreateWithFlags(&ev_g1,   cudaEventDisableTiming);
        cudaEventCreateWithFlags(&ev_csr,  cudaEventDisableTiming);
        cudaEventCreateWithFlags(&ev_b,    cudaEventDisableTiming);
        cudaFuncSetAttribute(gemm1_v2, cudaFuncAttributeMaxDynamicSharedMemorySize, SMEM_G1);
    }

    const int nb_scan = cdiv(n, 1024);
    const int nA = ((n / 2) + 255) & ~255;
    const int nB = n - nA;

    // ---- fork -------------------------------------------------------------
    cudaEventRecord(ev_fork, 0);
    cudaStreamWaitEvent(s1, ev_fork, 0);
    cudaStreamWaitEvent(s2, ev_fork, 0);

    cudaMemsetAsync(p_counts, 0, n * sizeof(int), s1);                 // (1)
    hist_kernel <<<cdiv(E, 256), 256, 0, s1>>>(ei, E);                 // (2)
    scan_part1  <<<nb_scan, 1024, 0, s1>>>(n);                         // (3)

    wprep_kernel<<<128, 256, 0, s2>>>(W1);                             // (4)
    cudaEventRecord(ev_w, s2);

    cudaStreamWaitEvent(0, ev_w, 0);
    gemm1_v2<<<cdiv(n, 128), 256, SMEM_G1>>>(x, n, p_h1,               // (5) profiled
                                             as1, ad1, p_as1, p_ad1);
    cudaEventRecord(ev_g1, 0);

    scan_part23 <<<nb_scan, 1024, 0, s1>>>(nb_scan, n, E);             // (6)
    scatter_kernel<<<cdiv(E, 256), 256, 0, s1>>>(ei, E);               // (7)
    cudaEventRecord(ev_csr, s1);

    // ---- B half on s1 overlapping A half on main ---------------------------
    cudaStreamWaitEvent(s1, ev_g1, 0);
    agg1_kernel<<<cdiv(nB * 32, 256), 256, 0, s1>>>(b1, nA, n);
    gemm2_kernel<40, 5, 32><<<cdiv(nB, 256), 256, 0, s1>>>(
        p_hf1 + (size_t)nA * 64, nB, 64, W2, p_h2 + (size_t)nA * 40,
        as2, ad2, p_as2 + nA, p_ad2 + nA);
    cudaEventRecord(ev_b, s1);

    cudaStreamWaitEvent(0, ev_csr, 0);
    agg1_kernel<<<cdiv(nA * 32, 256), 256>>>(b1, 0, nA);
    gemm2_kernel<40, 5, 32><<<cdiv(nA, 256), 256>>>(
        p_hf1, nA, 64, W2, p_h2, as2, ad2, p_as2, p_ad2);

    cudaStreamWaitEvent(0, ev_b, 0);
    agg2_kernel<<<cdiv(n * 32, 256), 256>>>(b2, out, n);
}